// round 8
// baseline (speedup 1.0000x reference)
#include <cuda_runtime.h>
#include <cuda_fp16.h>
#include <math.h>
#include <stdint.h>

// Problem constants (fixed by the dataset)
#define NNODES 50000
#define HDIM   768
#define D1DIM  256
#define NOUT   512        // 2*D1: [A | B] per node
#define NEDGES 200000

// GEMM tiling: 128x128 block, BK=32, fp16 mma.sync m16n8k16
#define BM 128
#define BN 128
#define BK 32
#define LDH 40                       // fp16 smem row stride (halves)
#define STG_H (BM * LDH)             // halves per tile stage (5120)
#define NBST 3                       // B cp.async stages
#define NAST 2                       // A (reg->smem) stages

#define EDGE_WARPS 8
#define EDGES_PER_WARP 2
#define EDGES_PER_BLOCK (EDGE_WARPS * EDGES_PER_WARP)     // 16
#define EDGE_BLOCKS (NEDGES / EDGES_PER_BLOCK)            // 12500

// Scratch (static device globals; no runtime allocation)
__device__ __half g_Wh[(size_t)NOUT * HDIM];         // Wcat rows in fp16 (768 KB)
__device__ __half g_AB[(size_t)NNODES * NOUT];       // ~51 MB -> L2-resident
__device__ float  g_partials[2 * EDGE_BLOCKS];

// ---------------------------------------------------------------------------
// helpers
// ---------------------------------------------------------------------------
__device__ __forceinline__ void cp_async16(void* smem, const void* gmem) {
    unsigned s = (unsigned)__cvta_generic_to_shared(smem);
    asm volatile("cp.async.cg.shared.global [%0], [%1], 16;" :: "r"(s), "l"(gmem));
}
#define CP_COMMIT  asm volatile("cp.async.commit_group;")
#define CP_WAIT1   asm volatile("cp.async.wait_group 1;")
#define CP_WAIT0   asm volatile("cp.async.wait_group 0;")

__device__ __forceinline__ void ldsm_x4(unsigned& r0, unsigned& r1,
                                        unsigned& r2, unsigned& r3, unsigned addr) {
    asm volatile("ldmatrix.sync.aligned.m8n8.x4.shared.b16 {%0,%1,%2,%3}, [%4];"
                 : "=r"(r0), "=r"(r1), "=r"(r2), "=r"(r3) : "r"(addr));
}

#define MMA_F16(c, a, b)                                                      \
    asm volatile(                                                             \
        "mma.sync.aligned.m16n8k16.row.col.f32.f16.f16.f32 "                  \
        "{%0,%1,%2,%3},{%4,%5,%6,%7},{%8,%9},{%0,%1,%2,%3};"                  \
        : "+f"((c)[0]), "+f"((c)[1]), "+f"((c)[2]), "+f"((c)[3])              \
        : "r"((a)[0]), "r"((a)[1]), "r"((a)[2]), "r"((a)[3]),                 \
          "r"((b)[0]), "r"((b)[1]))

// Exact-grade gelu: erf via Abramowitz-Stegun 7.1.26 (abs err ~1.5e-7).
// Uses MUFU.RCP + MUFU.EX2 instead of erff's long fma/alu sequence.
__device__ __forceinline__ float gelu_f(float v) {
    const float z  = 0.70710678118654752f * v;
    const float az = fabsf(z);
    const float t  = __fdividef(1.0f, fmaf(0.3275911f, az, 1.0f));
    float p = fmaf(t, 1.061405429f, -1.453152027f);
    p = fmaf(t, p, 1.421413741f);
    p = fmaf(t, p, -0.284496736f);
    p = fmaf(t, p, 0.254829592f);
    p = p * t;
    const float e  = __expf(-az * az);
    float er = fmaf(-p, e, 1.0f);
    er = copysignf(er, z);
    const float hv = 0.5f * v;
    return fmaf(hv, er, hv);
}

// ---------------------------------------------------------------------------
// Pre-pass: Wcat rows -> fp16 (tiny; 768 KB)
// ---------------------------------------------------------------------------
__global__ __launch_bounds__(256) void conv_w_kernel(const float* __restrict__ W1)
{
    const int i = blockIdx.x * 256 + threadIdx.x;   // float4 index
    const int n4 = NOUT * HDIM / 4;
    if (i < n4) {
        const int e = i * 4;
        const int n = e / HDIM;
        const int k = e % HDIM;
        const float* src = (n < D1DIM)
            ? (W1 + (size_t)n * (2 * HDIM) + k)
            : (W1 + (size_t)(n - D1DIM) * (2 * HDIM) + HDIM + k);
        float4 v = *(const float4*)src;
        __half2 h0 = __floats2half2_rn(v.x, v.y);
        __half2 h1 = __floats2half2_rn(v.z, v.w);
        uint2 o; o.x = *(uint32_t*)&h0; o.y = *(uint32_t*)&h1;
        *(uint2*)(g_Wh + e) = o;
    }
}

// ---------------------------------------------------------------------------
// Kernel 1: AB = x @ Wcat^T via fp16 mma.sync m16n8k16 (fp32 accumulate).
// A path: fp32 LDG.128 (prefetched one iter ahead) -> F2FP -> STS fp16
//         (fused conversion; no conv_x pre-pass, x read once in fp32).
// B path: 3-stage cp.async from fp16 W. Fragments via ldmatrix.x4.
// Grid (4, 391): 4 n-blocks of one m-tile co-scheduled -> x shared in L2.
// ---------------------------------------------------------------------------
__global__ __launch_bounds__(256) void gemm_kernel(const float* __restrict__ x)
{
    extern __shared__ __align__(16) __half smem[];
    __half* sA = smem;                    // 2 stages
    __half* sB = smem + NAST * STG_H;     // 3 stages

    const int tid  = threadIdx.x;
    const int lane = tid & 31;
    const int warp = tid >> 5;
    const int wm   = (warp >> 2) * 64;     // warp m offset in block
    const int wn   = (warp & 3) * 32;      // warp n offset in block

    const int n0 = blockIdx.x * BN;
    const int m0 = blockIdx.y * BM;

    // ---- A: per-thread fp32 row segment (16 floats = 4x float4) ----
    const int arow = tid >> 1;             // 0..127
    const int ah   = (tid & 1) * 16;       // 0 or 16
    int gmA = m0 + arow; if (gmA > NNODES - 1) gmA = NNODES - 1;
    const float* pX = x + (size_t)gmA * HDIM + ah;
    __half* aDst0 = sA + arow * LDH + ah;

    // ---- B: per-thread cp.async coords (2 chunks of 16B per stage) ----
    const int brow0 = tid >> 2;            // 0..63
    const int bc4   = tid & 3;
    const int brow1 = brow0 + 64;
    const __half* pB0 = g_Wh + (size_t)(n0 + brow0) * HDIM + bc4 * 8;
    const __half* pB1 = g_Wh + (size_t)(n0 + brow1) * HDIM + bc4 * 8;

    unsigned smA16[NAST], smB16[NBST];
    #pragma unroll
    for (int st = 0; st < NAST; st++)
        smA16[st] = (unsigned)__cvta_generic_to_shared(sA + st * STG_H);
    #pragma unroll
    for (int st = 0; st < NBST; st++)
        smB16[st] = (unsigned)__cvta_generic_to_shared(sB + st * STG_H);

    // ldmatrix per-lane offsets (bytes within tile, row stride 80B)
    const int aRow = wm + (lane & 15);                         // + mi*16
    const unsigned aKB = (unsigned)(lane >> 4) * 16u;          // 0 or 16
    const int bRow = wn + ((lane >> 4) & 1) * 8 + (lane & 7);  // + p*16
    const unsigned bKB = (unsigned)((lane >> 3) & 1) * 16u;    // 0 or 16

    float acc[4][4][4];
    #pragma unroll
    for (int i = 0; i < 4; i++)
        #pragma unroll
        for (int j = 0; j < 4; j++)
            #pragma unroll
            for (int v = 0; v < 4; v++) acc[i][j][v] = 0.f;

    // ---- prologue ----
    float4 rA[4];
    #pragma unroll
    for (int q = 0; q < 4; q++) rA[q] = *(const float4*)(pX + q * 4);   // it=0
    #pragma unroll
    for (int st = 0; st < 2; st++) {       // B stages 0,1
        const int kt = st * BK;
        cp_async16(sB + st * STG_H + brow0 * LDH + bc4 * 8, pB0 + kt);
        cp_async16(sB + st * STG_H + brow1 * LDH + bc4 * 8, pB1 + kt);
        CP_COMMIT;
    }

    const int NIT = HDIM / BK;  // 24
    for (int it = 0; it < NIT; ++it) {
        if (it < NIT - 1) { CP_WAIT1; } else { CP_WAIT0; }

        // ---- convert + store A regs (iter it) to fp16 smem stage it&1 ----
        {
            __half2 h[8];
            #pragma unroll
            for (int q = 0; q < 4; q++) {
                h[2 * q]     = __floats2half2_rn(rA[q].x, rA[q].y);
                h[2 * q + 1] = __floats2half2_rn(rA[q].z, rA[q].w);
            }
            __half* dst = aDst0 + (it & 1) * STG_H;
            uint4 o0 = make_uint4(*(uint32_t*)&h[0], *(uint32_t*)&h[1],
                                  *(uint32_t*)&h[2], *(uint32_t*)&h[3]);
            uint4 o1 = make_uint4(*(uint32_t*)&h[4], *(uint32_t*)&h[5],
                                  *(uint32_t*)&h[6], *(uint32_t*)&h[7]);
            *(uint4*)(dst)     = o0;
            *(uint4*)(dst + 8) = o1;
        }
        __syncthreads();   // A16[it&1] + B16[it%3] ready for all warps

        // ---- prefetch A regs for it+1 (consumed next iter -> latency hidden) ----
        if (it + 1 < NIT) {
            const float* p = pX + (it + 1) * BK;
            #pragma unroll
            for (int q = 0; q < 4; q++) rA[q] = *(const float4*)(p + q * 4);
        }
        // ---- B cp.async stage it+2 ----
        if (it + 2 < NIT) {
            const int st = (it + 2) % NBST;
            const int kt = (it + 2) * BK;
            cp_async16(sB + st * STG_H + brow0 * LDH + bc4 * 8, pB0 + kt);
            cp_async16(sB + st * STG_H + brow1 * LDH + bc4 * 8, pB1 + kt);
            CP_COMMIT;
        }

        const unsigned bA = smA16[it & 1];
        const unsigned bB = smB16[it % NBST];
        // ---- compute: 2 k=16 steps ----
        #pragma unroll
        for (int kk = 0; kk < 2; kk++) {
            unsigned af[4][4], bf[4][2];
            #pragma unroll
            for (int mi = 0; mi < 4; mi++) {
                unsigned addr = bA + (unsigned)(aRow + mi * 16) * (LDH * 2)
                              + (unsigned)kk * 32u + aKB;
                ldsm_x4(af[mi][0], af[mi][1], af[mi][2], af[mi][3], addr);
            }
            #pragma unroll
            for (int p = 0; p < 2; p++) {
                unsigned addr = bB + (unsigned)(bRow + p * 16) * (LDH * 2)
                              + (unsigned)kk * 32u + bKB;
                ldsm_x4(bf[2 * p][0], bf[2 * p][1], bf[2 * p + 1][0], bf[2 * p + 1][1], addr);
            }
            #pragma unroll
            for (int mi = 0; mi < 4; mi++)
                #pragma unroll
                for (int ni = 0; ni < 4; ni++)
                    MMA_F16(acc[mi][ni], af[mi], bf[ni]);
        }
    }

    // ---- store to fp16 AB ----
    const int g  = lane >> 2;
    const int tg = lane & 3;
    #pragma unroll
    for (int mi = 0; mi < 4; mi++) {
        #pragma unroll
        for (int ni = 0; ni < 4; ni++) {
            const int gm = m0 + wm + mi * 16 + g;
            const int gn = n0 + wn + ni * 8 + 2 * tg;
            if (gm < NNODES) {
                *(__half2*)(g_AB + (size_t)gm * NOUT + gn) =
                    __floats2half2_rn(acc[mi][ni][0], acc[mi][ni][1]);
            }
            if (gm + 8 < NNODES) {
                *(__half2*)(g_AB + (size_t)(gm + 8) * NOUT + gn) =
                    __floats2half2_rn(acc[mi][ni][2], acc[mi][ni][3]);
            }
        }
    }
}

// ---------------------------------------------------------------------------
// Kernel 2: per-edge MLP tail. 2 edges per warp; 4 gathers in flight.
// ---------------------------------------------------------------------------
__global__ __launch_bounds__(256) void edge_kernel(const float* __restrict__ b1,
                                                   const float* __restrict__ W2,
                                                   const float* __restrict__ b2,
                                                   const float* __restrict__ cw,
                                                   const int* __restrict__ esrc,
                                                   const int* __restrict__ edst,
                                                   const int* __restrict__ labels,
                                                   float* __restrict__ out)
{
    __shared__ float s_b1[D1DIM];
    __shared__ float s_W2[2 * D1DIM];
    __shared__ float s_wn[EDGE_WARPS];
    __shared__ float s_w[EDGE_WARPS];

    const int tid  = threadIdx.x;
    const int lane = tid & 31;
    const int warp = tid >> 5;

    if (tid < D1DIM) s_b1[tid] = b1[tid];
    s_W2[tid]       = W2[tid];
    s_W2[tid + 256] = W2[tid + 256];
    __syncthreads();

    const int e0 = blockIdx.x * EDGES_PER_BLOCK + warp * EDGES_PER_WARP;
    const int e1 = e0 + 1;
    const int j0 = lane * 8;

    const int s0 = esrc[e0], d0 = edst[e0];
    const int s1 = esrc[e1], d1 = edst[e1];
    const uint4 va0 = *(const uint4*)(g_AB + (size_t)s0 * NOUT + j0);
    const uint4 vb0 = *(const uint4*)(g_AB + (size_t)d0 * NOUT + D1DIM + j0);
    const uint4 va1 = *(const uint4*)(g_AB + (size_t)s1 * NOUT + j0);
    const uint4 vb1 = *(const uint4*)(g_AB + (size_t)d1 * NOUT + D1DIM + j0);

    float a00 = 0.f, a01 = 0.f, a10 = 0.f, a11 = 0.f;
    {
        const __half2* ha0 = (const __half2*)&va0;
        const __half2* hb0 = (const __half2*)&vb0;
        const __half2* ha1 = (const __half2*)&va1;
        const __half2* hb1 = (const __half2*)&vb1;
        #pragma unroll
        for (int t = 0; t < 4; t++) {
            const int j = j0 + 2 * t;
            const float w0a = s_W2[j],       w0b = s_W2[j + 1];
            const float w1a = s_W2[256 + j], w1b = s_W2[256 + j + 1];
            const float bja = s_b1[j], bjb = s_b1[j + 1];
            {
                const float2 fa = __half22float2(ha0[t]);
                const float2 fb = __half22float2(hb0[t]);
                const float h0 = gelu_f(fa.x + fb.x + bja);
                a00 = fmaf(h0, w0a, a00); a01 = fmaf(h0, w1a, a01);
                const float h1 = gelu_f(fa.y + fb.y + bjb);
                a00 = fmaf(h1, w0b, a00); a01 = fmaf(h1, w1b, a01);
            }
            {
                const float2 fa = __half22float2(ha1[t]);
                const float2 fb = __half22float2(hb1[t]);
                const float h0 = gelu_f(fa.x + fb.x + bja);
                a10 = fmaf(h0, w0a, a10); a11 = fmaf(h0, w1a, a11);
                const float h1 = gelu_f(fa.y + fb.y + bjb);
                a10 = fmaf(h1, w0b, a10); a11 = fmaf(h1, w1b, a11);
            }
        }
    }
    #pragma unroll
    for (int o = 16; o > 0; o >>= 1) {
        a00 += __shfl_xor_sync(0xFFFFFFFFu, a00, o);
        a01 += __shfl_xor_sync(0xFFFFFFFFu, a01, o);
        a10 += __shfl_xor_sync(0xFFFFFFFFu, a10, o);
        a11 += __shfl_xor_sync(0xFFFFFFFFu, a11, o);
    }

    float wn = 0.f, wsum = 0.f;
    if (lane == 0) {
        const float bb0 = __ldg(&b2[0]);
        const float bb1 = __ldg(&b2[1]);
        {
            const float l0 = a00 + bb0, l1 = a01 + bb1;
            const float m  = fmaxf(l0, l1);
            const float x0 = expf(l0 - m), x1 = expf(l1 - m);
            const float ssum = x0 + x1, inv = 1.0f / ssum;
            out[1 + 2 * e0]     = x0 * inv;
            out[1 + 2 * e0 + 1] = x1 * inv;
            const int lb = labels[e0];
            const float logp = ((lb ? l1 : l0) - m) - logf(ssum);
            const float w = __ldg(&cw[lb]);
            wn += -w * logp; wsum += w;
        }
        {
            const float l0 = a10 + bb0, l1 = a11 + bb1;
            const float m  = fmaxf(l0, l1);
            const float x0 = expf(l0 - m), x1 = expf(l1 - m);
            const float ssum = x0 + x1, inv = 1.0f / ssum;
            out[1 + 2 * e1]     = x0 * inv;
            out[1 + 2 * e1 + 1] = x1 * inv;
            const int lb = labels[e1];
            const float logp = ((lb ? l1 : l0) - m) - logf(ssum);
            const float w = __ldg(&cw[lb]);
            wn += -w * logp; wsum += w;
        }
        s_wn[warp] = wn; s_w[warp] = wsum;
    }
    __syncthreads();
    if (tid == 0) {
        float a = 0.f, b = 0.f;
        #pragma unroll
        for (int i = 0; i < EDGE_WARPS; i++) { a += s_wn[i]; b += s_w[i]; }
        g_partials[blockIdx.x]               = a;
        g_partials[EDGE_BLOCKS + blockIdx.x] = b;
    }
}

// ---------------------------------------------------------------------------
// Kernel 3: deterministic final reduction -> loss at out[0]
// ---------------------------------------------------------------------------
__global__ __launch_bounds__(256) void finalize_kernel(float* __restrict__ out)
{
    __shared__ float sa[256];
    __shared__ float sb[256];
    const int tid = threadIdx.x;
    float a = 0.f, b = 0.f;
    for (int i = tid; i < EDGE_BLOCKS; i += 256) {
        a += g_partials[i];
        b += g_partials[EDGE_BLOCKS + i];
    }
    sa[tid] = a; sb[tid] = b;
    __syncthreads();
    for (int o = 128; o > 0; o >>= 1) {
        if (tid < o) { sa[tid] += sa[tid + o]; sb[tid] += sb[tid + o]; }
        __syncthreads();
    }
    if (tid == 0) out[0] = sa[0] / sb[0];
}

// ---------------------------------------------------------------------------
extern "C" void kernel_launch(void* const* d_in, const int* in_sizes, int n_in,
                              void* d_out, int out_size)
{
    const float* x      = (const float*)d_in[0];
    const float* W1     = (const float*)d_in[1];
    const float* b1     = (const float*)d_in[2];
    const float* W2     = (const float*)d_in[3];
    const float* b2     = (const float*)d_in[4];
    const float* cw     = (const float*)d_in[5];
    const int*   esrc   = (const int*)d_in[6];
    const int*   edst   = (const int*)d_in[7];
    const int*   labels = (const int*)d_in[8];
    float* out = (float*)d_out;

    const int GEMM_SMEM = (NAST + NBST) * STG_H * (int)sizeof(__half);  // 51200
    cudaFuncSetAttribute(gemm_kernel,
                         cudaFuncAttributeMaxDynamicSharedMemorySize, GEMM_SMEM);

    conv_w_kernel<<<(NOUT * HDIM / 4 + 255) / 256, 256>>>(W1);

    dim3 ggrid(NOUT / BN, (NNODES + BM - 1) / BM);   // (4, 391)
    gemm_kernel<<<ggrid, 256, GEMM_SMEM>>>(x);
    edge_kernel<<<EDGE_BLOCKS, 256>>>(b1, W2, b2, cw, esrc, edst, labels, out);
    finalize_kernel<<<1, 256>>>(out);
}

// round 9
// speedup vs baseline: 1.0678x; 1.0678x over previous
#include <cuda_runtime.h>
#include <cuda_fp16.h>
#include <math.h>
#include <stdint.h>

// Problem constants (fixed by the dataset)
#define NNODES 50000
#define HDIM   768
#define D1DIM  256
#define NOUT   512        // 2*D1: [A | B] per node
#define NEDGES 200000

// GEMM tiling: 128x128 block, BK=32, fp16 mma.sync m16n8k16, 3-stage cp.async
#define BM 128
#define BN 128
#define BK 32
#define LDH 40            // smem row stride in halves (80B); conflict-free ldmatrix
#define NSTAGE 3
#define STAGE_H (BM * LDH)            // halves per tile stage (5120)

#define EDGE_WARPS 8
#define EDGES_PER_WARP 4
#define EDGES_PER_BLOCK (EDGE_WARPS * EDGES_PER_WARP)     // 32
#define EDGE_BLOCKS (NEDGES / EDGES_PER_BLOCK)            // 6250

// Scratch (static device globals; no runtime allocation)
__device__ __half g_xh[(size_t)NNODES * HDIM];       // x in fp16 (~77 MB)
__device__ __half g_Wh[(size_t)NOUT * HDIM];         // Wcat rows in fp16 (768 KB)
__device__ __half g_AB[(size_t)NNODES * NOUT];       // ~51 MB -> L2-resident
__device__ float  g_partials[2 * EDGE_BLOCKS];

// ---------------------------------------------------------------------------
// helpers
// ---------------------------------------------------------------------------
__device__ __forceinline__ void cp_async16(void* smem, const void* gmem) {
    unsigned s = (unsigned)__cvta_generic_to_shared(smem);
    asm volatile("cp.async.cg.shared.global [%0], [%1], 16;" :: "r"(s), "l"(gmem));
}
#define CP_COMMIT  asm volatile("cp.async.commit_group;")
#define CP_WAIT1   asm volatile("cp.async.wait_group 1;")
#define CP_WAIT0   asm volatile("cp.async.wait_group 0;")

__device__ __forceinline__ void ldsm_x4(unsigned& r0, unsigned& r1,
                                        unsigned& r2, unsigned& r3, unsigned addr) {
    asm volatile("ldmatrix.sync.aligned.m8n8.x4.shared.b16 {%0,%1,%2,%3}, [%4];"
                 : "=r"(r0), "=r"(r1), "=r"(r2), "=r"(r3) : "r"(addr));
}

#define MMA_F16(c, a, b)                                                      \
    asm volatile(                                                             \
        "mma.sync.aligned.m16n8k16.row.col.f32.f16.f16.f32 "                  \
        "{%0,%1,%2,%3},{%4,%5,%6,%7},{%8,%9},{%0,%1,%2,%3};"                  \
        : "+f"((c)[0]), "+f"((c)[1]), "+f"((c)[2]), "+f"((c)[3])              \
        : "r"((a)[0]), "r"((a)[1]), "r"((a)[2]), "r"((a)[3]),                 \
          "r"((b)[0]), "r"((b)[1]))

// Exact-grade gelu: erf via Abramowitz-Stegun 7.1.26 (abs err ~1.5e-7).
// MUFU.RCP + MUFU.EX2 on the idle MUFU pipe instead of erff's fma/alu chain.
__device__ __forceinline__ float gelu_f(float v) {
    const float z  = 0.70710678118654752f * v;
    const float az = fabsf(z);
    const float t  = __fdividef(1.0f, fmaf(0.3275911f, az, 1.0f));
    float p = fmaf(t, 1.061405429f, -1.453152027f);
    p = fmaf(t, p, 1.421413741f);
    p = fmaf(t, p, -0.284496736f);
    p = fmaf(t, p, 0.254829592f);
    p = p * t;
    const float e  = __expf(-az * az);
    float er = fmaf(-p, e, 1.0f);
    er = copysignf(er, z);
    const float hv = 0.5f * v;
    return fmaf(hv, er, hv);
}

// ---------------------------------------------------------------------------
// Conversion pre-passes: fp32 -> fp16 globals
// ---------------------------------------------------------------------------
__global__ __launch_bounds__(256) void conv_x_kernel(const float* __restrict__ x)
{
    const size_t i = (size_t)blockIdx.x * 256 + threadIdx.x;   // float4 index
    const size_t n4 = (size_t)NNODES * HDIM / 4;
    if (i < n4) {
        float4 v = *(const float4*)(x + i * 4);
        __half2 h0 = __floats2half2_rn(v.x, v.y);
        __half2 h1 = __floats2half2_rn(v.z, v.w);
        uint2 o; o.x = *(uint32_t*)&h0; o.y = *(uint32_t*)&h1;
        *(uint2*)(g_xh + i * 4) = o;
    }
}

__global__ __launch_bounds__(256) void conv_w_kernel(const float* __restrict__ W1)
{
    const int i = blockIdx.x * 256 + threadIdx.x;   // float4 index
    const int n4 = NOUT * HDIM / 4;
    if (i < n4) {
        const int e = i * 4;
        const int n = e / HDIM;
        const int k = e % HDIM;
        const float* src = (n < D1DIM)
            ? (W1 + (size_t)n * (2 * HDIM) + k)
            : (W1 + (size_t)(n - D1DIM) * (2 * HDIM) + HDIM + k);
        float4 v = *(const float4*)src;
        __half2 h0 = __floats2half2_rn(v.x, v.y);
        __half2 h1 = __floats2half2_rn(v.z, v.w);
        uint2 o; o.x = *(uint32_t*)&h0; o.y = *(uint32_t*)&h1;
        *(uint2*)(g_Wh + e) = o;
    }
}

// ---------------------------------------------------------------------------
// Kernel 1: AB = x_h @ W_h^T via fp16 mma.sync m16n8k16 (fp32 accumulate).
// 3-stage cp.async pipeline, ldmatrix.x4 b16 fragment loads (R7 structure —
// benched fastest; GEMM is at ~93% of the HMMA pipe ceiling).
// ---------------------------------------------------------------------------
__global__ __launch_bounds__(256) void gemm_kernel()
{
    extern __shared__ __align__(16) __half smem[];
    __half* sA = smem;
    __half* sB = smem + NSTAGE * STAGE_H;

    const int tid  = threadIdx.x;
    const int lane = tid & 31;
    const int warp = tid >> 5;
    const int wm   = (warp >> 2) * 64;
    const int wn   = (warp & 3) * 32;

    const int m0 = blockIdx.x * BM;
    const int n0 = blockIdx.y * BN;

    const int row0 = tid >> 2;             // 0..63
    const int c4   = tid & 3;
    const int row1 = row0 + 64;
    int gm0 = m0 + row0; if (gm0 > NNODES - 1) gm0 = NNODES - 1;
    int gm1 = m0 + row1; if (gm1 > NNODES - 1) gm1 = NNODES - 1;
    const __half* pA0 = g_xh + (size_t)gm0 * HDIM + c4 * 8;
    const __half* pA1 = g_xh + (size_t)gm1 * HDIM + c4 * 8;
    const __half* pB0 = g_Wh + (size_t)(n0 + row0) * HDIM + c4 * 8;
    const __half* pB1 = g_Wh + (size_t)(n0 + row1) * HDIM + c4 * 8;

    unsigned smA[NSTAGE], smB[NSTAGE];
    #pragma unroll
    for (int st = 0; st < NSTAGE; st++) {
        smA[st] = (unsigned)__cvta_generic_to_shared(sA + st * STAGE_H);
        smB[st] = (unsigned)__cvta_generic_to_shared(sB + st * STAGE_H);
    }

    const int aRow = wm + (lane & 15);
    const unsigned aKB = (unsigned)(lane >> 4) * 16u;
    const int bRow = wn + ((lane >> 4) & 1) * 8 + (lane & 7);
    const unsigned bKB = (unsigned)((lane >> 3) & 1) * 16u;

    float acc[4][4][4];
    #pragma unroll
    for (int i = 0; i < 4; i++)
        #pragma unroll
        for (int j = 0; j < 4; j++)
            #pragma unroll
            for (int v = 0; v < 4; v++) acc[i][j][v] = 0.f;

    #pragma unroll
    for (int st = 0; st < 2; st++) {
        const int kt = st * BK;
        cp_async16(sA + st * STAGE_H + row0 * LDH + c4 * 8, pA0 + kt);
        cp_async16(sA + st * STAGE_H + row1 * LDH + c4 * 8, pA1 + kt);
        cp_async16(sB + st * STAGE_H + row0 * LDH + c4 * 8, pB0 + kt);
        cp_async16(sB + st * STAGE_H + row1 * LDH + c4 * 8, pB1 + kt);
        CP_COMMIT;
    }

    const int NIT = HDIM / BK;  // 24
    int s = 0;
    for (int it = 0; it < NIT; ++it) {
        if (it < NIT - 1) { CP_WAIT1; } else { CP_WAIT0; }
        __syncthreads();

        if (it + 2 < NIT) {
            const int st = (it + 2) % NSTAGE;
            const int kt = (it + 2) * BK;
            cp_async16(sA + st * STAGE_H + row0 * LDH + c4 * 8, pA0 + kt);
            cp_async16(sA + st * STAGE_H + row1 * LDH + c4 * 8, pA1 + kt);
            cp_async16(sB + st * STAGE_H + row0 * LDH + c4 * 8, pB0 + kt);
            cp_async16(sB + st * STAGE_H + row1 * LDH + c4 * 8, pB1 + kt);
            CP_COMMIT;
        }

        const unsigned bA = smA[s];
        const unsigned bB = smB[s];
        #pragma unroll
        for (int kk = 0; kk < 2; kk++) {
            unsigned af[4][4], bf[4][2];
            #pragma unroll
            for (int mi = 0; mi < 4; mi++) {
                unsigned addr = bA + (unsigned)(aRow + mi * 16) * (LDH * 2)
                              + (unsigned)kk * 32u + aKB;
                ldsm_x4(af[mi][0], af[mi][1], af[mi][2], af[mi][3], addr);
            }
            #pragma unroll
            for (int p = 0; p < 2; p++) {
                unsigned addr = bB + (unsigned)(bRow + p * 16) * (LDH * 2)
                              + (unsigned)kk * 32u + bKB;
                ldsm_x4(bf[2 * p][0], bf[2 * p][1], bf[2 * p + 1][0], bf[2 * p + 1][1], addr);
            }
            #pragma unroll
            for (int mi = 0; mi < 4; mi++)
                #pragma unroll
                for (int ni = 0; ni < 4; ni++)
                    MMA_F16(acc[mi][ni], af[mi], bf[ni]);
        }
        s = (s + 1 == NSTAGE) ? 0 : s + 1;
    }

    const int g  = lane >> 2;
    const int tg = lane & 3;
    #pragma unroll
    for (int mi = 0; mi < 4; mi++) {
        #pragma unroll
        for (int ni = 0; ni < 4; ni++) {
            const int gm = m0 + wm + mi * 16 + g;
            const int gn = n0 + wn + ni * 8 + 2 * tg;
            if (gm < NNODES) {
                *(__half2*)(g_AB + (size_t)gm * NOUT + gn) =
                    __floats2half2_rn(acc[mi][ni][0], acc[mi][ni][1]);
            }
            if (gm + 8 < NNODES) {
                *(__half2*)(g_AB + (size_t)(gm + 8) * NOUT + gn) =
                    __floats2half2_rn(acc[mi][ni][2], acc[mi][ni][3]);
            }
        }
    }
}

// ---------------------------------------------------------------------------
// Kernel 2: per-edge MLP tail. 4 edges per warp; 8 gathers in flight.
// ---------------------------------------------------------------------------
__global__ __launch_bounds__(256) void edge_kernel(const float* __restrict__ b1,
                                                   const float* __restrict__ W2,
                                                   const float* __restrict__ b2,
                                                   const float* __restrict__ cw,
                                                   const int* __restrict__ esrc,
                                                   const int* __restrict__ edst,
                                                   const int* __restrict__ labels,
                                                   float* __restrict__ out)
{
    __shared__ float s_b1[D1DIM];
    __shared__ float s_W2[2 * D1DIM];
    __shared__ float s_wn[EDGE_WARPS];
    __shared__ float s_w[EDGE_WARPS];

    const int tid  = threadIdx.x;
    const int lane = tid & 31;
    const int warp = tid >> 5;

    if (tid < D1DIM) s_b1[tid] = b1[tid];
    s_W2[tid]       = W2[tid];
    s_W2[tid + 256] = W2[tid + 256];
    __syncthreads();

    const int eb = blockIdx.x * EDGES_PER_BLOCK + warp * EDGES_PER_WARP;
    const int j0 = lane * 8;

    // issue all 8 gathers before compute
    uint4 va[EDGES_PER_WARP], vb[EDGES_PER_WARP];
    #pragma unroll
    for (int q = 0; q < EDGES_PER_WARP; q++) {
        const int s = esrc[eb + q];
        const int d = edst[eb + q];
        va[q] = *(const uint4*)(g_AB + (size_t)s * NOUT + j0);
        vb[q] = *(const uint4*)(g_AB + (size_t)d * NOUT + D1DIM + j0);
    }

    float ac0[EDGES_PER_WARP], ac1[EDGES_PER_WARP];
    #pragma unroll
    for (int q = 0; q < EDGES_PER_WARP; q++) { ac0[q] = 0.f; ac1[q] = 0.f; }

    #pragma unroll
    for (int t = 0; t < 4; t++) {
        const int j = j0 + 2 * t;
        const float w0a = s_W2[j],       w0b = s_W2[j + 1];
        const float w1a = s_W2[256 + j], w1b = s_W2[256 + j + 1];
        const float bja = s_b1[j], bjb = s_b1[j + 1];
        #pragma unroll
        for (int q = 0; q < EDGES_PER_WARP; q++) {
            const float2 fa = __half22float2(((const __half2*)&va[q])[t]);
            const float2 fb = __half22float2(((const __half2*)&vb[q])[t]);
            const float h0 = gelu_f(fa.x + fb.x + bja);
            ac0[q] = fmaf(h0, w0a, ac0[q]); ac1[q] = fmaf(h0, w1a, ac1[q]);
            const float h1 = gelu_f(fa.y + fb.y + bjb);
            ac0[q] = fmaf(h1, w0b, ac0[q]); ac1[q] = fmaf(h1, w1b, ac1[q]);
        }
    }
    #pragma unroll
    for (int o = 16; o > 0; o >>= 1) {
        #pragma unroll
        for (int q = 0; q < EDGES_PER_WARP; q++) {
            ac0[q] += __shfl_xor_sync(0xFFFFFFFFu, ac0[q], o);
            ac1[q] += __shfl_xor_sync(0xFFFFFFFFu, ac1[q], o);
        }
    }

    if (lane == 0) {
        const float bb0 = __ldg(&b2[0]);
        const float bb1 = __ldg(&b2[1]);
        float wn = 0.f, wsum = 0.f;
        #pragma unroll
        for (int q = 0; q < EDGES_PER_WARP; q++) {
            const int e = eb + q;
            const float l0 = ac0[q] + bb0, l1 = ac1[q] + bb1;
            const float m  = fmaxf(l0, l1);
            const float x0 = expf(l0 - m), x1 = expf(l1 - m);
            const float ssum = x0 + x1, inv = 1.0f / ssum;
            out[1 + 2 * e]     = x0 * inv;
            out[1 + 2 * e + 1] = x1 * inv;
            const int lb = labels[e];
            const float logp = ((lb ? l1 : l0) - m) - logf(ssum);
            const float w = __ldg(&cw[lb]);
            wn += -w * logp; wsum += w;
        }
        s_wn[warp] = wn; s_w[warp] = wsum;
    }
    __syncthreads();
    if (tid == 0) {
        float a = 0.f, b = 0.f;
        #pragma unroll
        for (int i = 0; i < EDGE_WARPS; i++) { a += s_wn[i]; b += s_w[i]; }
        g_partials[blockIdx.x]               = a;
        g_partials[EDGE_BLOCKS + blockIdx.x] = b;
    }
}

// ---------------------------------------------------------------------------
// Kernel 3: deterministic final reduction -> loss at out[0]
// ---------------------------------------------------------------------------
__global__ __launch_bounds__(256) void finalize_kernel(float* __restrict__ out)
{
    __shared__ float sa[256];
    __shared__ float sb[256];
    const int tid = threadIdx.x;
    float a = 0.f, b = 0.f;
    // EDGE_BLOCKS = 6250: ~25 strided iterations, 2 loads each
    for (int i = tid; i < EDGE_BLOCKS; i += 256) {
        a += g_partials[i];
        b += g_partials[EDGE_BLOCKS + i];
    }
    sa[tid] = a; sb[tid] = b;
    __syncthreads();
    for (int o = 128; o > 0; o >>= 1) {
        if (tid < o) { sa[tid] += sa[tid + o]; sb[tid] += sb[tid + o]; }
        __syncthreads();
    }
    if (tid == 0) out[0] = sa[0] / sb[0];
}

// ---------------------------------------------------------------------------
extern "C" void kernel_launch(void* const* d_in, const int* in_sizes, int n_in,
                              void* d_out, int out_size)
{
    const float* x      = (const float*)d_in[0];
    const float* W1     = (const float*)d_in[1];
    const float* b1     = (const float*)d_in[2];
    const float* W2     = (const float*)d_in[3];
    const float* b2     = (const float*)d_in[4];
    const float* cw     = (const float*)d_in[5];
    const int*   esrc   = (const int*)d_in[6];
    const int*   edst   = (const int*)d_in[7];
    const int*   labels = (const int*)d_in[8];
    float* out = (float*)d_out;

    const int GEMM_SMEM = 2 * NSTAGE * STAGE_H * (int)sizeof(__half);  // 61440
    cudaFuncSetAttribute(gemm_kernel,
                         cudaFuncAttributeMaxDynamicSharedMemorySize, GEMM_SMEM);

    const int nx4 = (int)(((size_t)NNODES * HDIM / 4 + 255) / 256);   // 37500
    conv_x_kernel<<<nx4, 256>>>(x);
    conv_w_kernel<<<(NOUT * HDIM / 4 + 255) / 256, 256>>>(W1);

    dim3 ggrid((NNODES + BM - 1) / BM, NOUT / BN);   // 391 x 4
    gemm_kernel<<<ggrid, 256, GEMM_SMEM>>>();
    edge_kernel<<<EDGE_BLOCKS, 256>>>(b1, W2, b2, cw, esrc, edst, labels, out);
    finalize_kernel<<<1, 256>>>(out);
}

// round 10
// speedup vs baseline: 1.1532x; 1.0800x over previous
#include <cuda_runtime.h>
#include <cuda_fp16.h>
#include <math.h>
#include <stdint.h>

// Problem constants (fixed by the dataset)
#define NNODES 50000
#define HDIM   768
#define D1DIM  256
#define NOUT   512        // 2*D1: [A | B] per node
#define NEDGES 200000

// GEMM tiling: 128x128 block, BK=32, fp16 mma.sync m16n8k16, 3-stage cp.async
#define BM 128
#define BN 128
#define BK 32
#define LDH 40            // smem row stride in halves (80B); conflict-free ldmatrix
#define NSTAGE 3
#define STAGE_H (BM * LDH)            // halves per tile stage (5120)

#define EDGE_WARPS 8
#define EDGES_PER_WARP 4
#define EDGES_PER_BLOCK (EDGE_WARPS * EDGES_PER_WARP)     // 32
#define EDGE_BLOCKS (NEDGES / EDGES_PER_BLOCK)            // 6250

// Scratch (static device globals; no runtime allocation)
__device__ __half g_xh[(size_t)NNODES * HDIM];       // x in fp16 (~77 MB)
__device__ __half g_Wh[(size_t)NOUT * HDIM];         // Wcat rows in fp16 (768 KB)
__device__ __half g_AB[(size_t)NNODES * NOUT];       // ~51 MB -> L2-resident
__device__ float  g_partials[2 * EDGE_BLOCKS];

// ---------------------------------------------------------------------------
// helpers
// ---------------------------------------------------------------------------
__device__ __forceinline__ void cp_async16(void* smem, const void* gmem) {
    unsigned s = (unsigned)__cvta_generic_to_shared(smem);
    asm volatile("cp.async.cg.shared.global [%0], [%1], 16;" :: "r"(s), "l"(gmem));
}
#define CP_COMMIT  asm volatile("cp.async.commit_group;")
#define CP_WAIT1   asm volatile("cp.async.wait_group 1;")
#define CP_WAIT0   asm volatile("cp.async.wait_group 0;")

__device__ __forceinline__ void ldsm_x4(unsigned& r0, unsigned& r1,
                                        unsigned& r2, unsigned& r3, unsigned addr) {
    asm volatile("ldmatrix.sync.aligned.m8n8.x4.shared.b16 {%0,%1,%2,%3}, [%4];"
                 : "=r"(r0), "=r"(r1), "=r"(r2), "=r"(r3) : "r"(addr));
}

#define MMA_F16(c, a, b)                                                      \
    asm volatile(                                                             \
        "mma.sync.aligned.m16n8k16.row.col.f32.f16.f16.f32 "                  \
        "{%0,%1,%2,%3},{%4,%5,%6,%7},{%8,%9},{%0,%1,%2,%3};"                  \
        : "+f"((c)[0]), "+f"((c)[1]), "+f"((c)[2]), "+f"((c)[3])              \
        : "r"((a)[0]), "r"((a)[1]), "r"((a)[2]), "r"((a)[3]),                 \
          "r"((b)[0]), "r"((b)[1]))

// gelu via tanh form + HW tanh.approx.f32 (MUFU pipe): 6 instructions.
// 0.5*v*(1 + tanh(0.7978845608*v + 0.0356774081*v^3))
__device__ __forceinline__ float gelu_f(float v) {
    const float w = v * v;
    const float u = v * fmaf(0.0356774081f, w, 0.7978845608f);
    float t;
    asm("tanh.approx.f32 %0, %1;" : "=f"(t) : "f"(u));
    const float hv = 0.5f * v;
    return fmaf(hv, t, hv);
}

// ---------------------------------------------------------------------------
// Conversion pre-passes: fp32 -> fp16 globals
// ---------------------------------------------------------------------------
__global__ __launch_bounds__(256) void conv_x_kernel(const float* __restrict__ x)
{
    const size_t i = (size_t)blockIdx.x * 256 + threadIdx.x;   // float4 index
    const size_t n4 = (size_t)NNODES * HDIM / 4;
    if (i < n4) {
        float4 v = *(const float4*)(x + i * 4);
        __half2 h0 = __floats2half2_rn(v.x, v.y);
        __half2 h1 = __floats2half2_rn(v.z, v.w);
        uint2 o; o.x = *(uint32_t*)&h0; o.y = *(uint32_t*)&h1;
        *(uint2*)(g_xh + i * 4) = o;
    }
}

__global__ __launch_bounds__(256) void conv_w_kernel(const float* __restrict__ W1)
{
    const int i = blockIdx.x * 256 + threadIdx.x;   // float4 index
    const int n4 = NOUT * HDIM / 4;
    if (i < n4) {
        const int e = i * 4;
        const int n = e / HDIM;
        const int k = e % HDIM;
        const float* src = (n < D1DIM)
            ? (W1 + (size_t)n * (2 * HDIM) + k)
            : (W1 + (size_t)(n - D1DIM) * (2 * HDIM) + HDIM + k);
        float4 v = *(const float4*)src;
        __half2 h0 = __floats2half2_rn(v.x, v.y);
        __half2 h1 = __floats2half2_rn(v.z, v.w);
        uint2 o; o.x = *(uint32_t*)&h0; o.y = *(uint32_t*)&h1;
        *(uint2*)(g_Wh + e) = o;
    }
}

// ---------------------------------------------------------------------------
// Kernel 1: AB = x_h @ W_h^T via fp16 mma.sync m16n8k16 (fp32 accumulate).
// 3-stage cp.async pipeline, ldmatrix.x4 b16 fragment loads (R7 structure —
// benched fastest; GEMM is at ~93% of the HMMA pipe ceiling).
// ---------------------------------------------------------------------------
__global__ __launch_bounds__(256) void gemm_kernel()
{
    extern __shared__ __align__(16) __half smem[];
    __half* sA = smem;
    __half* sB = smem + NSTAGE * STAGE_H;

    const int tid  = threadIdx.x;
    const int lane = tid & 31;
    const int warp = tid >> 5;
    const int wm   = (warp >> 2) * 64;
    const int wn   = (warp & 3) * 32;

    const int m0 = blockIdx.x * BM;
    const int n0 = blockIdx.y * BN;

    const int row0 = tid >> 2;             // 0..63
    const int c4   = tid & 3;
    const int row1 = row0 + 64;
    int gm0 = m0 + row0; if (gm0 > NNODES - 1) gm0 = NNODES - 1;
    int gm1 = m0 + row1; if (gm1 > NNODES - 1) gm1 = NNODES - 1;
    const __half* pA0 = g_xh + (size_t)gm0 * HDIM + c4 * 8;
    const __half* pA1 = g_xh + (size_t)gm1 * HDIM + c4 * 8;
    const __half* pB0 = g_Wh + (size_t)(n0 + row0) * HDIM + c4 * 8;
    const __half* pB1 = g_Wh + (size_t)(n0 + row1) * HDIM + c4 * 8;

    unsigned smA[NSTAGE], smB[NSTAGE];
    #pragma unroll
    for (int st = 0; st < NSTAGE; st++) {
        smA[st] = (unsigned)__cvta_generic_to_shared(sA + st * STAGE_H);
        smB[st] = (unsigned)__cvta_generic_to_shared(sB + st * STAGE_H);
    }

    const int aRow = wm + (lane & 15);
    const unsigned aKB = (unsigned)(lane >> 4) * 16u;
    const int bRow = wn + ((lane >> 4) & 1) * 8 + (lane & 7);
    const unsigned bKB = (unsigned)((lane >> 3) & 1) * 16u;

    float acc[4][4][4];
    #pragma unroll
    for (int i = 0; i < 4; i++)
        #pragma unroll
        for (int j = 0; j < 4; j++)
            #pragma unroll
            for (int v = 0; v < 4; v++) acc[i][j][v] = 0.f;

    #pragma unroll
    for (int st = 0; st < 2; st++) {
        const int kt = st * BK;
        cp_async16(sA + st * STAGE_H + row0 * LDH + c4 * 8, pA0 + kt);
        cp_async16(sA + st * STAGE_H + row1 * LDH + c4 * 8, pA1 + kt);
        cp_async16(sB + st * STAGE_H + row0 * LDH + c4 * 8, pB0 + kt);
        cp_async16(sB + st * STAGE_H + row1 * LDH + c4 * 8, pB1 + kt);
        CP_COMMIT;
    }

    const int NIT = HDIM / BK;  // 24
    int s = 0;
    for (int it = 0; it < NIT; ++it) {
        if (it < NIT - 1) { CP_WAIT1; } else { CP_WAIT0; }
        __syncthreads();

        if (it + 2 < NIT) {
            const int st = (it + 2) % NSTAGE;
            const int kt = (it + 2) * BK;
            cp_async16(sA + st * STAGE_H + row0 * LDH + c4 * 8, pA0 + kt);
            cp_async16(sA + st * STAGE_H + row1 * LDH + c4 * 8, pA1 + kt);
            cp_async16(sB + st * STAGE_H + row0 * LDH + c4 * 8, pB0 + kt);
            cp_async16(sB + st * STAGE_H + row1 * LDH + c4 * 8, pB1 + kt);
            CP_COMMIT;
        }

        const unsigned bA = smA[s];
        const unsigned bB = smB[s];
        #pragma unroll
        for (int kk = 0; kk < 2; kk++) {
            unsigned af[4][4], bf[4][2];
            #pragma unroll
            for (int mi = 0; mi < 4; mi++) {
                unsigned addr = bA + (unsigned)(aRow + mi * 16) * (LDH * 2)
                              + (unsigned)kk * 32u + aKB;
                ldsm_x4(af[mi][0], af[mi][1], af[mi][2], af[mi][3], addr);
            }
            #pragma unroll
            for (int p = 0; p < 2; p++) {
                unsigned addr = bB + (unsigned)(bRow + p * 16) * (LDH * 2)
                              + (unsigned)kk * 32u + bKB;
                ldsm_x4(bf[2 * p][0], bf[2 * p][1], bf[2 * p + 1][0], bf[2 * p + 1][1], addr);
            }
            #pragma unroll
            for (int mi = 0; mi < 4; mi++)
                #pragma unroll
                for (int ni = 0; ni < 4; ni++)
                    MMA_F16(acc[mi][ni], af[mi], bf[ni]);
        }
        s = (s + 1 == NSTAGE) ? 0 : s + 1;
    }

    const int g  = lane >> 2;
    const int tg = lane & 3;
    #pragma unroll
    for (int mi = 0; mi < 4; mi++) {
        #pragma unroll
        for (int ni = 0; ni < 4; ni++) {
            const int gm = m0 + wm + mi * 16 + g;
            const int gn = n0 + wn + ni * 8 + 2 * tg;
            if (gm < NNODES) {
                *(__half2*)(g_AB + (size_t)gm * NOUT + gn) =
                    __floats2half2_rn(acc[mi][ni][0], acc[mi][ni][1]);
            }
            if (gm + 8 < NNODES) {
                *(__half2*)(g_AB + (size_t)(gm + 8) * NOUT + gn) =
                    __floats2half2_rn(acc[mi][ni][2], acc[mi][ni][3]);
            }
        }
    }
}

// ---------------------------------------------------------------------------
// Kernel 2: per-edge MLP tail. 4 edges per warp; 8 gathers in flight.
// ---------------------------------------------------------------------------
__global__ __launch_bounds__(256) void edge_kernel(const float* __restrict__ b1,
                                                   const float* __restrict__ W2,
                                                   const float* __restrict__ b2,
                                                   const float* __restrict__ cw,
                                                   const int* __restrict__ esrc,
                                                   const int* __restrict__ edst,
                                                   const int* __restrict__ labels,
                                                   float* __restrict__ out)
{
    __shared__ float s_b1[D1DIM];
    __shared__ float s_W2[2 * D1DIM];
    __shared__ float s_wn[EDGE_WARPS];
    __shared__ float s_w[EDGE_WARPS];

    const int tid  = threadIdx.x;
    const int lane = tid & 31;
    const int warp = tid >> 5;

    if (tid < D1DIM) s_b1[tid] = b1[tid];
    s_W2[tid]       = W2[tid];
    s_W2[tid + 256] = W2[tid + 256];
    __syncthreads();

    const int eb = blockIdx.x * EDGES_PER_BLOCK + warp * EDGES_PER_WARP;
    const int j0 = lane * 8;

    // issue all 8 gathers before compute
    uint4 va[EDGES_PER_WARP], vb[EDGES_PER_WARP];
    #pragma unroll
    for (int q = 0; q < EDGES_PER_WARP; q++) {
        const int s = esrc[eb + q];
        const int d = edst[eb + q];
        va[q] = *(const uint4*)(g_AB + (size_t)s * NOUT + j0);
        vb[q] = *(const uint4*)(g_AB + (size_t)d * NOUT + D1DIM + j0);
    }

    float ac0[EDGES_PER_WARP], ac1[EDGES_PER_WARP];
    #pragma unroll
    for (int q = 0; q < EDGES_PER_WARP; q++) { ac0[q] = 0.f; ac1[q] = 0.f; }

    #pragma unroll
    for (int t = 0; t < 4; t++) {
        const int j = j0 + 2 * t;
        const float w0a = s_W2[j],       w0b = s_W2[j + 1];
        const float w1a = s_W2[256 + j], w1b = s_W2[256 + j + 1];
        const float bja = s_b1[j], bjb = s_b1[j + 1];
        #pragma unroll
        for (int q = 0; q < EDGES_PER_WARP; q++) {
            const float2 fa = __half22float2(((const __half2*)&va[q])[t]);
            const float2 fb = __half22float2(((const __half2*)&vb[q])[t]);
            const float h0 = gelu_f(fa.x + fb.x + bja);
            ac0[q] = fmaf(h0, w0a, ac0[q]); ac1[q] = fmaf(h0, w1a, ac1[q]);
            const float h1 = gelu_f(fa.y + fb.y + bjb);
            ac0[q] = fmaf(h1, w0b, ac0[q]); ac1[q] = fmaf(h1, w1b, ac1[q]);
        }
    }
    #pragma unroll
    for (int o = 16; o > 0; o >>= 1) {
        #pragma unroll
        for (int q = 0; q < EDGES_PER_WARP; q++) {
            ac0[q] += __shfl_xor_sync(0xFFFFFFFFu, ac0[q], o);
            ac1[q] += __shfl_xor_sync(0xFFFFFFFFu, ac1[q], o);
        }
    }

    if (lane == 0) {
        const float bb0 = __ldg(&b2[0]);
        const float bb1 = __ldg(&b2[1]);
        float wn = 0.f, wsum = 0.f;
        #pragma unroll
        for (int q = 0; q < EDGES_PER_WARP; q++) {
            const int e = eb + q;
            const float l0 = ac0[q] + bb0, l1 = ac1[q] + bb1;
            const float m  = fmaxf(l0, l1);
            const float x0 = expf(l0 - m), x1 = expf(l1 - m);
            const float ssum = x0 + x1, inv = 1.0f / ssum;
            out[1 + 2 * e]     = x0 * inv;
            out[1 + 2 * e + 1] = x1 * inv;
            const int lb = labels[e];
            const float logp = ((lb ? l1 : l0) - m) - logf(ssum);
            const float w = __ldg(&cw[lb]);
            wn += -w * logp; wsum += w;
        }
        s_wn[warp] = wn; s_w[warp] = wsum;
    }
    __syncthreads();
    if (tid == 0) {
        float a = 0.f, b = 0.f;
        #pragma unroll
        for (int i = 0; i < EDGE_WARPS; i++) { a += s_wn[i]; b += s_w[i]; }
        g_partials[blockIdx.x]               = a;
        g_partials[EDGE_BLOCKS + blockIdx.x] = b;
    }
}

// ---------------------------------------------------------------------------
// Kernel 3: deterministic final reduction -> loss at out[0]
// ---------------------------------------------------------------------------
__global__ __launch_bounds__(256) void finalize_kernel(float* __restrict__ out)
{
    __shared__ float sa[256];
    __shared__ float sb[256];
    const int tid = threadIdx.x;
    float a = 0.f, b = 0.f;
    for (int i = tid; i < EDGE_BLOCKS; i += 256) {
        a += g_partials[i];
        b += g_partials[EDGE_BLOCKS + i];
    }
    sa[tid] = a; sb[tid] = b;
    __syncthreads();
    for (int o = 128; o > 0; o >>= 1) {
        if (tid < o) { sa[tid] += sa[tid + o]; sb[tid] += sb[tid + o]; }
        __syncthreads();
    }
    if (tid == 0) out[0] = sa[0] / sb[0];
}

// ---------------------------------------------------------------------------
extern "C" void kernel_launch(void* const* d_in, const int* in_sizes, int n_in,
                              void* d_out, int out_size)
{
    const float* x      = (const float*)d_in[0];
    const float* W1     = (const float*)d_in[1];
    const float* b1     = (const float*)d_in[2];
    const float* W2     = (const float*)d_in[3];
    const float* b2     = (const float*)d_in[4];
    const float* cw     = (const float*)d_in[5];
    const int*   esrc   = (const int*)d_in[6];
    const int*   edst   = (const int*)d_in[7];
    const int*   labels = (const int*)d_in[8];
    float* out = (float*)d_out;

    const int GEMM_SMEM = 2 * NSTAGE * STAGE_H * (int)sizeof(__half);  // 61440
    cudaFuncSetAttribute(gemm_kernel,
                         cudaFuncAttributeMaxDynamicSharedMemorySize, GEMM_SMEM);

    const int nx4 = (int)(((size_t)NNODES * HDIM / 4 + 255) / 256);   // 37500
    conv_x_kernel<<<nx4, 256>>>(x);
    conv_w_kernel<<<(NOUT * HDIM / 4 + 255) / 256, 256>>>(W1);

    dim3 ggrid((NNODES + BM - 1) / BM, NOUT / BN);   // 391 x 4
    gemm_kernel<<<ggrid, 256, GEMM_SMEM>>>();
    edge_kernel<<<EDGE_BLOCKS, 256>>>(b1, W2, b2, cw, esrc, edst, labels, out);
    finalize_kernel<<<1, 256>>>(out);
}

// round 11
// speedup vs baseline: 1.1844x; 1.0270x over previous
#include <cuda_runtime.h>
#include <cuda_fp16.h>
#include <math.h>
#include <stdint.h>

// Problem constants (fixed by the dataset)
#define NNODES 50000
#define HDIM   768
#define D1DIM  256
#define NOUT   512        // 2*D1: [A | B] per node
#define NEDGES 200000

// GEMM tiling: 128x128 block, BK=32, fp16 mma.sync m16n8k16, 3-stage cp.async
#define BM 128
#define BN 128
#define BK 32
#define LDH 40            // smem row stride in halves (80B); conflict-free ldmatrix
#define NSTAGE 3
#define STAGE_H (BM * LDH)            // halves per tile stage (5120)

#define EDGE_WARPS 8
#define EDGES_PER_WARP 4
#define EDGES_PER_BLOCK (EDGE_WARPS * EDGES_PER_WARP)     // 32
#define EDGE_BLOCKS (NEDGES / EDGES_PER_BLOCK)            // 6250

// Scratch (static device globals; no runtime allocation)
__device__ __half g_xh[(size_t)NNODES * HDIM];       // x in fp16 (~77 MB)
__device__ __half g_Wh[(size_t)NOUT * HDIM];         // Wcat rows in fp16 (768 KB)
__device__ __half g_AB[(size_t)NNODES * NOUT];       // ~51 MB -> L2-resident
__device__ float  g_partials[2 * EDGE_BLOCKS];

// ---------------------------------------------------------------------------
// helpers
// ---------------------------------------------------------------------------
__device__ __forceinline__ void cp_async16(void* smem, const void* gmem) {
    unsigned s = (unsigned)__cvta_generic_to_shared(smem);
    asm volatile("cp.async.cg.shared.global [%0], [%1], 16;" :: "r"(s), "l"(gmem));
}
#define CP_COMMIT  asm volatile("cp.async.commit_group;")
#define CP_WAIT1   asm volatile("cp.async.wait_group 1;")
#define CP_WAIT0   asm volatile("cp.async.wait_group 0;")

__device__ __forceinline__ void ldsm_x4(unsigned& r0, unsigned& r1,
                                        unsigned& r2, unsigned& r3, unsigned addr) {
    asm volatile("ldmatrix.sync.aligned.m8n8.x4.shared.b16 {%0,%1,%2,%3}, [%4];"
                 : "=r"(r0), "=r"(r1), "=r"(r2), "=r"(r3) : "r"(addr));
}

#define MMA_F16(c, a, b)                                                      \
    asm volatile(                                                             \
        "mma.sync.aligned.m16n8k16.row.col.f32.f16.f16.f32 "                  \
        "{%0,%1,%2,%3},{%4,%5,%6,%7},{%8,%9},{%0,%1,%2,%3};"                  \
        : "+f"((c)[0]), "+f"((c)[1]), "+f"((c)[2]), "+f"((c)[3])              \
        : "r"((a)[0]), "r"((a)[1]), "r"((a)[2]), "r"((a)[3]),                 \
          "r"((b)[0]), "r"((b)[1]))

// packed half2 tanh on the MUFU pipe
__device__ __forceinline__ __half2 tanh_h2(__half2 x) {
    __half2 y;
    asm("tanh.approx.f16x2 %0, %1;"
        : "=r"(reinterpret_cast<unsigned&>(y))
        : "r"(reinterpret_cast<unsigned&>(x)));
    return y;
}

// ---------------------------------------------------------------------------
// Conversion pre-passes: fp32 -> fp16 globals
// ---------------------------------------------------------------------------
__global__ __launch_bounds__(256) void conv_x_kernel(const float* __restrict__ x)
{
    const size_t i = (size_t)blockIdx.x * 256 + threadIdx.x;   // float4 index
    const size_t n4 = (size_t)NNODES * HDIM / 4;
    if (i < n4) {
        float4 v = *(const float4*)(x + i * 4);
        __half2 h0 = __floats2half2_rn(v.x, v.y);
        __half2 h1 = __floats2half2_rn(v.z, v.w);
        uint2 o; o.x = *(uint32_t*)&h0; o.y = *(uint32_t*)&h1;
        *(uint2*)(g_xh + i * 4) = o;
    }
}

__global__ __launch_bounds__(256) void conv_w_kernel(const float* __restrict__ W1)
{
    const int i = blockIdx.x * 256 + threadIdx.x;   // float4 index
    const int n4 = NOUT * HDIM / 4;
    if (i < n4) {
        const int e = i * 4;
        const int n = e / HDIM;
        const int k = e % HDIM;
        const float* src = (n < D1DIM)
            ? (W1 + (size_t)n * (2 * HDIM) + k)
            : (W1 + (size_t)(n - D1DIM) * (2 * HDIM) + HDIM + k);
        float4 v = *(const float4*)src;
        __half2 h0 = __floats2half2_rn(v.x, v.y);
        __half2 h1 = __floats2half2_rn(v.z, v.w);
        uint2 o; o.x = *(uint32_t*)&h0; o.y = *(uint32_t*)&h1;
        *(uint2*)(g_Wh + e) = o;
    }
}

// ---------------------------------------------------------------------------
// Kernel 1: AB = x_h @ W_h^T via fp16 mma.sync m16n8k16 (fp32 accumulate).
// 3-stage cp.async pipeline, ldmatrix.x4 b16 fragment loads (benched fastest;
// GEMM runs at ~93% of the fp16 HMMA pipe ceiling).
// ---------------------------------------------------------------------------
__global__ __launch_bounds__(256) void gemm_kernel()
{
    extern __shared__ __align__(16) __half smem[];
    __half* sA = smem;
    __half* sB = smem + NSTAGE * STAGE_H;

    const int tid  = threadIdx.x;
    const int lane = tid & 31;
    const int warp = tid >> 5;
    const int wm   = (warp >> 2) * 64;
    const int wn   = (warp & 3) * 32;

    const int m0 = blockIdx.x * BM;
    const int n0 = blockIdx.y * BN;

    const int row0 = tid >> 2;             // 0..63
    const int c4   = tid & 3;
    const int row1 = row0 + 64;
    int gm0 = m0 + row0; if (gm0 > NNODES - 1) gm0 = NNODES - 1;
    int gm1 = m0 + row1; if (gm1 > NNODES - 1) gm1 = NNODES - 1;
    const __half* pA0 = g_xh + (size_t)gm0 * HDIM + c4 * 8;
    const __half* pA1 = g_xh + (size_t)gm1 * HDIM + c4 * 8;
    const __half* pB0 = g_Wh + (size_t)(n0 + row0) * HDIM + c4 * 8;
    const __half* pB1 = g_Wh + (size_t)(n0 + row1) * HDIM + c4 * 8;

    unsigned smA[NSTAGE], smB[NSTAGE];
    #pragma unroll
    for (int st = 0; st < NSTAGE; st++) {
        smA[st] = (unsigned)__cvta_generic_to_shared(sA + st * STAGE_H);
        smB[st] = (unsigned)__cvta_generic_to_shared(sB + st * STAGE_H);
    }

    const int aRow = wm + (lane & 15);
    const unsigned aKB = (unsigned)(lane >> 4) * 16u;
    const int bRow = wn + ((lane >> 4) & 1) * 8 + (lane & 7);
    const unsigned bKB = (unsigned)((lane >> 3) & 1) * 16u;

    float acc[4][4][4];
    #pragma unroll
    for (int i = 0; i < 4; i++)
        #pragma unroll
        for (int j = 0; j < 4; j++)
            #pragma unroll
            for (int v = 0; v < 4; v++) acc[i][j][v] = 0.f;

    #pragma unroll
    for (int st = 0; st < 2; st++) {
        const int kt = st * BK;
        cp_async16(sA + st * STAGE_H + row0 * LDH + c4 * 8, pA0 + kt);
        cp_async16(sA + st * STAGE_H + row1 * LDH + c4 * 8, pA1 + kt);
        cp_async16(sB + st * STAGE_H + row0 * LDH + c4 * 8, pB0 + kt);
        cp_async16(sB + st * STAGE_H + row1 * LDH + c4 * 8, pB1 + kt);
        CP_COMMIT;
    }

    const int NIT = HDIM / BK;  // 24
    int s = 0;
    for (int it = 0; it < NIT; ++it) {
        if (it < NIT - 1) { CP_WAIT1; } else { CP_WAIT0; }
        __syncthreads();

        if (it + 2 < NIT) {
            const int st = (it + 2) % NSTAGE;
            const int kt = (it + 2) * BK;
            cp_async16(sA + st * STAGE_H + row0 * LDH + c4 * 8, pA0 + kt);
            cp_async16(sA + st * STAGE_H + row1 * LDH + c4 * 8, pA1 + kt);
            cp_async16(sB + st * STAGE_H + row0 * LDH + c4 * 8, pB0 + kt);
            cp_async16(sB + st * STAGE_H + row1 * LDH + c4 * 8, pB1 + kt);
            CP_COMMIT;
        }

        const unsigned bA = smA[s];
        const unsigned bB = smB[s];
        #pragma unroll
        for (int kk = 0; kk < 2; kk++) {
            unsigned af[4][4], bf[4][2];
            #pragma unroll
            for (int mi = 0; mi < 4; mi++) {
                unsigned addr = bA + (unsigned)(aRow + mi * 16) * (LDH * 2)
                              + (unsigned)kk * 32u + aKB;
                ldsm_x4(af[mi][0], af[mi][1], af[mi][2], af[mi][3], addr);
            }
            #pragma unroll
            for (int p = 0; p < 2; p++) {
                unsigned addr = bB + (unsigned)(bRow + p * 16) * (LDH * 2)
                              + (unsigned)kk * 32u + bKB;
                ldsm_x4(bf[2 * p][0], bf[2 * p][1], bf[2 * p + 1][0], bf[2 * p + 1][1], addr);
            }
            #pragma unroll
            for (int mi = 0; mi < 4; mi++)
                #pragma unroll
                for (int ni = 0; ni < 4; ni++)
                    MMA_F16(acc[mi][ni], af[mi], bf[ni]);
        }
        s = (s + 1 == NSTAGE) ? 0 : s + 1;
    }

    const int g  = lane >> 2;
    const int tg = lane & 3;
    #pragma unroll
    for (int mi = 0; mi < 4; mi++) {
        #pragma unroll
        for (int ni = 0; ni < 4; ni++) {
            const int gm = m0 + wm + mi * 16 + g;
            const int gn = n0 + wn + ni * 8 + 2 * tg;
            if (gm < NNODES) {
                *(__half2*)(g_AB + (size_t)gm * NOUT + gn) =
                    __floats2half2_rn(acc[mi][ni][0], acc[mi][ni][1]);
            }
            if (gm + 8 < NNODES) {
                *(__half2*)(g_AB + (size_t)(gm + 8) * NOUT + gn) =
                    __floats2half2_rn(acc[mi][ni][2], acc[mi][ni][3]);
            }
        }
    }
}

// ---------------------------------------------------------------------------
// Kernel 2: per-edge MLP tail, packed half2 math.
// 4 edges per warp; 8 gathers in flight; gelu via tanh.approx.f16x2.
// ---------------------------------------------------------------------------
__global__ __launch_bounds__(256) void edge_kernel(const float* __restrict__ b1,
                                                   const float* __restrict__ W2,
                                                   const float* __restrict__ b2,
                                                   const float* __restrict__ cw,
                                                   const int* __restrict__ esrc,
                                                   const int* __restrict__ edst,
                                                   const int* __restrict__ labels,
                                                   float* __restrict__ out)
{
    __shared__ __half2 s_b1h[D1DIM / 2];
    __shared__ __half2 s_w0h[D1DIM / 2];
    __shared__ __half2 s_w1h[D1DIM / 2];
    __shared__ float s_wn[EDGE_WARPS];
    __shared__ float s_w[EDGE_WARPS];

    const int tid  = threadIdx.x;
    const int lane = tid & 31;
    const int warp = tid >> 5;

    if (tid < D1DIM / 2) {
        s_b1h[tid] = __floats2half2_rn(b1[2 * tid], b1[2 * tid + 1]);
        s_w0h[tid] = __floats2half2_rn(W2[2 * tid], W2[2 * tid + 1]);
        s_w1h[tid] = __floats2half2_rn(W2[D1DIM + 2 * tid], W2[D1DIM + 2 * tid + 1]);
    }
    __syncthreads();

    const int eb = blockIdx.x * EDGES_PER_BLOCK + warp * EDGES_PER_WARP;
    const int j0 = lane * 8;          // 8 halves = 4 half2 per lane
    const int h0 = lane * 4;          // half2 base index

    // issue all 8 gathers before compute
    uint4 va[EDGES_PER_WARP], vb[EDGES_PER_WARP];
    #pragma unroll
    for (int q = 0; q < EDGES_PER_WARP; q++) {
        const int s = esrc[eb + q];
        const int d = edst[eb + q];
        va[q] = *(const uint4*)(g_AB + (size_t)s * NOUT + j0);
        vb[q] = *(const uint4*)(g_AB + (size_t)d * NOUT + D1DIM + j0);
    }

    const __half2 C0  = __float2half2_rn(0.7978845608f);
    const __half2 C1  = __float2half2_rn(0.0356774081f);
    const __half2 H05 = __float2half2_rn(0.5f);

    __half2 ac0[EDGES_PER_WARP], ac1[EDGES_PER_WARP];
    #pragma unroll
    for (int q = 0; q < EDGES_PER_WARP; q++) {
        ac0[q] = __float2half2_rn(0.f);
        ac1[q] = __float2half2_rn(0.f);
    }

    #pragma unroll
    for (int t = 0; t < 4; t++) {
        const __half2 bh = s_b1h[h0 + t];
        const __half2 w0 = s_w0h[h0 + t];
        const __half2 w1 = s_w1h[h0 + t];
        #pragma unroll
        for (int q = 0; q < EDGES_PER_WARP; q++) {
            const __half2 a2 = ((const __half2*)&va[q])[t];
            const __half2 b2h = ((const __half2*)&vb[q])[t];
            const __half2 v  = __hadd2(__hadd2(a2, b2h), bh);
            const __half2 w  = __hmul2(v, v);
            const __half2 u  = __hmul2(v, __hfma2(C1, w, C0));
            const __half2 th = tanh_h2(u);
            const __half2 hv = __hmul2(H05, v);
            const __half2 h  = __hfma2(hv, th, hv);
            ac0[q] = __hfma2(h, w0, ac0[q]);
            ac1[q] = __hfma2(h, w1, ac1[q]);
        }
    }

    // widen per-lane half2 accumulators (only 4 fp16 fma terms each) to fp32
    float f0[EDGES_PER_WARP], f1[EDGES_PER_WARP];
    #pragma unroll
    for (int q = 0; q < EDGES_PER_WARP; q++) {
        const float2 x0 = __half22float2(ac0[q]);
        const float2 x1 = __half22float2(ac1[q]);
        f0[q] = x0.x + x0.y;
        f1[q] = x1.x + x1.y;
    }
    #pragma unroll
    for (int o = 16; o > 0; o >>= 1) {
        #pragma unroll
        for (int q = 0; q < EDGES_PER_WARP; q++) {
            f0[q] += __shfl_xor_sync(0xFFFFFFFFu, f0[q], o);
            f1[q] += __shfl_xor_sync(0xFFFFFFFFu, f1[q], o);
        }
    }

    if (lane == 0) {
        const float bb0 = __ldg(&b2[0]);
        const float bb1 = __ldg(&b2[1]);
        float wn = 0.f, wsum = 0.f;
        #pragma unroll
        for (int q = 0; q < EDGES_PER_WARP; q++) {
            const int e = eb + q;
            const float l0 = f0[q] + bb0, l1 = f1[q] + bb1;
            const float m  = fmaxf(l0, l1);
            const float x0 = expf(l0 - m), x1 = expf(l1 - m);
            const float ssum = x0 + x1, inv = 1.0f / ssum;
            out[1 + 2 * e]     = x0 * inv;
            out[1 + 2 * e + 1] = x1 * inv;
            const int lb = labels[e];
            const float logp = ((lb ? l1 : l0) - m) - logf(ssum);
            const float w = __ldg(&cw[lb]);
            wn += -w * logp; wsum += w;
        }
        s_wn[warp] = wn; s_w[warp] = wsum;
    }
    __syncthreads();
    if (tid == 0) {
        float a = 0.f, b = 0.f;
        #pragma unroll
        for (int i = 0; i < EDGE_WARPS; i++) { a += s_wn[i]; b += s_w[i]; }
        g_partials[blockIdx.x]               = a;
        g_partials[EDGE_BLOCKS + blockIdx.x] = b;
    }
}

// ---------------------------------------------------------------------------
// Kernel 3: deterministic final reduction -> loss at out[0]
// ---------------------------------------------------------------------------
__global__ __launch_bounds__(256) void finalize_kernel(float* __restrict__ out)
{
    __shared__ float sa[256];
    __shared__ float sb[256];
    const int tid = threadIdx.x;
    float a = 0.f, b = 0.f;
    for (int i = tid; i < EDGE_BLOCKS; i += 256) {
        a += g_partials[i];
        b += g_partials[EDGE_BLOCKS + i];
    }
    sa[tid] = a; sb[tid] = b;
    __syncthreads();
    for (int o = 128; o > 0; o >>= 1) {
        if (tid < o) { sa[tid] += sa[tid + o]; sb[tid] += sb[tid + o]; }
        __syncthreads();
    }
    if (tid == 0) out[0] = sa[0] / sb[0];
}

// ---------------------------------------------------------------------------
extern "C" void kernel_launch(void* const* d_in, const int* in_sizes, int n_in,
                              void* d_out, int out_size)
{
    const float* x      = (const float*)d_in[0];
    const float* W1     = (const float*)d_in[1];
    const float* b1     = (const float*)d_in[2];
    const float* W2     = (const float*)d_in[3];
    const float* b2     = (const float*)d_in[4];
    const float* cw     = (const float*)d_in[5];
    const int*   esrc   = (const int*)d_in[6];
    const int*   edst   = (const int*)d_in[7];
    const int*   labels = (const int*)d_in[8];
    float* out = (float*)d_out;

    const int GEMM_SMEM = 2 * NSTAGE * STAGE_H * (int)sizeof(__half);  // 61440
    cudaFuncSetAttribute(gemm_kernel,
                         cudaFuncAttributeMaxDynamicSharedMemorySize, GEMM_SMEM);

    const int nx4 = (int)(((size_t)NNODES * HDIM / 4 + 255) / 256);   // 37500
    conv_x_kernel<<<nx4, 256>>>(x);
    conv_w_kernel<<<(NOUT * HDIM / 4 + 255) / 256, 256>>>(W1);

    dim3 ggrid((NNODES + BM - 1) / BM, NOUT / BN);   // 391 x 4
    gemm_kernel<<<ggrid, 256, GEMM_SMEM>>>();
    edge_kernel<<<EDGE_BLOCKS, 256>>>(b1, W2, b2, cw, esrc, edst, labels, out);
    finalize_kernel<<<1, 256>>>(out);
}

// round 12
// speedup vs baseline: 1.2449x; 1.0510x over previous
#include <cuda_runtime.h>
#include <cuda_fp16.h>
#include <math.h>
#include <stdint.h>

// Problem constants (fixed by the dataset)
#define NNODES 50000
#define HDIM   768
#define D1DIM  256
#define NOUT   512        // 2*D1: [A | B] per node
#define NEDGES 200000

// GEMM tiling: 128x128 block, BK=32, fp16 mma.sync m16n8k16, 3-stage cp.async
#define BM 128
#define BN 128
#define BK 32
#define LDH 40            // smem row stride in halves (80B); conflict-free ldmatrix
#define NSTAGE 3
#define STAGE_H (BM * LDH)            // halves per tile stage (5120)

#define EDGE_WARPS 8
#define EDGES_PER_WARP 4
#define EDGES_PER_BLOCK (EDGE_WARPS * EDGES_PER_WARP)     // 32
#define EDGE_BLOCKS (NEDGES / EDGES_PER_BLOCK)            // 6250

// Scratch (static device globals; no runtime allocation)
__device__ __half g_xh[(size_t)NNODES * HDIM];       // x in fp16 (~77 MB)
__device__ __half g_Wh[(size_t)NOUT * HDIM];         // Wcat rows in fp16 (768 KB)
__device__ __half g_AB[(size_t)NNODES * NOUT];       // ~51 MB -> L2-resident
__device__ float  g_partials[2 * EDGE_BLOCKS];

// ---------------------------------------------------------------------------
// helpers
// ---------------------------------------------------------------------------
__device__ __forceinline__ void cp_async16(void* smem, const void* gmem) {
    unsigned s = (unsigned)__cvta_generic_to_shared(smem);
    asm volatile("cp.async.cg.shared.global [%0], [%1], 16;" :: "r"(s), "l"(gmem));
}
#define CP_COMMIT  asm volatile("cp.async.commit_group;")
#define CP_WAIT1   asm volatile("cp.async.wait_group 1;")
#define CP_WAIT0   asm volatile("cp.async.wait_group 0;")

__device__ __forceinline__ void ldsm_x4(unsigned& r0, unsigned& r1,
                                        unsigned& r2, unsigned& r3, unsigned addr) {
    asm volatile("ldmatrix.sync.aligned.m8n8.x4.shared.b16 {%0,%1,%2,%3}, [%4];"
                 : "=r"(r0), "=r"(r1), "=r"(r2), "=r"(r3) : "r"(addr));
}

#define MMA_F16(c, a, b)                                                      \
    asm volatile(                                                             \
        "mma.sync.aligned.m16n8k16.row.col.f32.f16.f16.f32 "                  \
        "{%0,%1,%2,%3},{%4,%5,%6,%7},{%8,%9},{%0,%1,%2,%3};"                  \
        : "+f"((c)[0]), "+f"((c)[1]), "+f"((c)[2]), "+f"((c)[3])              \
        : "r"((a)[0]), "r"((a)[1]), "r"((a)[2]), "r"((a)[3]),                 \
          "r"((b)[0]), "r"((b)[1]))

// packed half2 tanh on the MUFU pipe
__device__ __forceinline__ __half2 tanh_h2(__half2 x) {
    __half2 y;
    asm("tanh.approx.f16x2 %0, %1;"
        : "=r"(reinterpret_cast<unsigned&>(y))
        : "r"(reinterpret_cast<unsigned&>(x)));
    return y;
}

// ---------------------------------------------------------------------------
// Conversion pre-passes: fp32 -> fp16 globals
// ---------------------------------------------------------------------------
__global__ __launch_bounds__(256) void conv_x_kernel(const float* __restrict__ x)
{
    const size_t i = (size_t)blockIdx.x * 256 + threadIdx.x;   // float4 index
    const size_t n4 = (size_t)NNODES * HDIM / 4;
    if (i < n4) {
        float4 v = *(const float4*)(x + i * 4);
        __half2 h0 = __floats2half2_rn(v.x, v.y);
        __half2 h1 = __floats2half2_rn(v.z, v.w);
        uint2 o; o.x = *(uint32_t*)&h0; o.y = *(uint32_t*)&h1;
        *(uint2*)(g_xh + i * 4) = o;
    }
}

__global__ __launch_bounds__(256) void conv_w_kernel(const float* __restrict__ W1)
{
    const int i = blockIdx.x * 256 + threadIdx.x;   // float4 index
    const int n4 = NOUT * HDIM / 4;
    if (i < n4) {
        const int e = i * 4;
        const int n = e / HDIM;
        const int k = e % HDIM;
        const float* src = (n < D1DIM)
            ? (W1 + (size_t)n * (2 * HDIM) + k)
            : (W1 + (size_t)(n - D1DIM) * (2 * HDIM) + HDIM + k);
        float4 v = *(const float4*)src;
        __half2 h0 = __floats2half2_rn(v.x, v.y);
        __half2 h1 = __floats2half2_rn(v.z, v.w);
        uint2 o; o.x = *(uint32_t*)&h0; o.y = *(uint32_t*)&h1;
        *(uint2*)(g_Wh + e) = o;
    }
}

// ---------------------------------------------------------------------------
// Kernel 1: AB = x_h @ W_h^T via fp16 mma.sync m16n8k16 (fp32 accumulate).
// 3-stage cp.async pipeline, ldmatrix.x4 b16 fragment loads (benched fastest;
// GEMM runs at ~93% of the fp16 HMMA pipe ceiling).
// ---------------------------------------------------------------------------
__global__ __launch_bounds__(256) void gemm_kernel()
{
    extern __shared__ __align__(16) __half smem[];
    __half* sA = smem;
    __half* sB = smem + NSTAGE * STAGE_H;

    const int tid  = threadIdx.x;
    const int lane = tid & 31;
    const int warp = tid >> 5;
    const int wm   = (warp >> 2) * 64;
    const int wn   = (warp & 3) * 32;

    const int m0 = blockIdx.x * BM;
    const int n0 = blockIdx.y * BN;

    const int row0 = tid >> 2;             // 0..63
    const int c4   = tid & 3;
    const int row1 = row0 + 64;
    int gm0 = m0 + row0; if (gm0 > NNODES - 1) gm0 = NNODES - 1;
    int gm1 = m0 + row1; if (gm1 > NNODES - 1) gm1 = NNODES - 1;
    const __half* pA0 = g_xh + (size_t)gm0 * HDIM + c4 * 8;
    const __half* pA1 = g_xh + (size_t)gm1 * HDIM + c4 * 8;
    const __half* pB0 = g_Wh + (size_t)(n0 + row0) * HDIM + c4 * 8;
    const __half* pB1 = g_Wh + (size_t)(n0 + row1) * HDIM + c4 * 8;

    unsigned smA[NSTAGE], smB[NSTAGE];
    #pragma unroll
    for (int st = 0; st < NSTAGE; st++) {
        smA[st] = (unsigned)__cvta_generic_to_shared(sA + st * STAGE_H);
        smB[st] = (unsigned)__cvta_generic_to_shared(sB + st * STAGE_H);
    }

    const int aRow = wm + (lane & 15);
    const unsigned aKB = (unsigned)(lane >> 4) * 16u;
    const int bRow = wn + ((lane >> 4) & 1) * 8 + (lane & 7);
    const unsigned bKB = (unsigned)((lane >> 3) & 1) * 16u;

    float acc[4][4][4];
    #pragma unroll
    for (int i = 0; i < 4; i++)
        #pragma unroll
        for (int j = 0; j < 4; j++)
            #pragma unroll
            for (int v = 0; v < 4; v++) acc[i][j][v] = 0.f;

    #pragma unroll
    for (int st = 0; st < 2; st++) {
        const int kt = st * BK;
        cp_async16(sA + st * STAGE_H + row0 * LDH + c4 * 8, pA0 + kt);
        cp_async16(sA + st * STAGE_H + row1 * LDH + c4 * 8, pA1 + kt);
        cp_async16(sB + st * STAGE_H + row0 * LDH + c4 * 8, pB0 + kt);
        cp_async16(sB + st * STAGE_H + row1 * LDH + c4 * 8, pB1 + kt);
        CP_COMMIT;
    }

    const int NIT = HDIM / BK;  // 24
    int s = 0;
    for (int it = 0; it < NIT; ++it) {
        if (it < NIT - 1) { CP_WAIT1; } else { CP_WAIT0; }
        __syncthreads();

        if (it + 2 < NIT) {
            const int st = (it + 2) % NSTAGE;
            const int kt = (it + 2) * BK;
            cp_async16(sA + st * STAGE_H + row0 * LDH + c4 * 8, pA0 + kt);
            cp_async16(sA + st * STAGE_H + row1 * LDH + c4 * 8, pA1 + kt);
            cp_async16(sB + st * STAGE_H + row0 * LDH + c4 * 8, pB0 + kt);
            cp_async16(sB + st * STAGE_H + row1 * LDH + c4 * 8, pB1 + kt);
            CP_COMMIT;
        }

        const unsigned bA = smA[s];
        const unsigned bB = smB[s];
        #pragma unroll
        for (int kk = 0; kk < 2; kk++) {
            unsigned af[4][4], bf[4][2];
            #pragma unroll
            for (int mi = 0; mi < 4; mi++) {
                unsigned addr = bA + (unsigned)(aRow + mi * 16) * (LDH * 2)
                              + (unsigned)kk * 32u + aKB;
                ldsm_x4(af[mi][0], af[mi][1], af[mi][2], af[mi][3], addr);
            }
            #pragma unroll
            for (int p = 0; p < 2; p++) {
                unsigned addr = bB + (unsigned)(bRow + p * 16) * (LDH * 2)
                              + (unsigned)kk * 32u + bKB;
                ldsm_x4(bf[2 * p][0], bf[2 * p][1], bf[2 * p + 1][0], bf[2 * p + 1][1], addr);
            }
            #pragma unroll
            for (int mi = 0; mi < 4; mi++)
                #pragma unroll
                for (int ni = 0; ni < 4; ni++)
                    MMA_F16(acc[mi][ni], af[mi], bf[ni]);
        }
        s = (s + 1 == NSTAGE) ? 0 : s + 1;
    }

    const int g  = lane >> 2;
    const int tg = lane & 3;
    #pragma unroll
    for (int mi = 0; mi < 4; mi++) {
        #pragma unroll
        for (int ni = 0; ni < 4; ni++) {
            const int gm = m0 + wm + mi * 16 + g;
            const int gn = n0 + wn + ni * 8 + 2 * tg;
            if (gm < NNODES) {
                *(__half2*)(g_AB + (size_t)gm * NOUT + gn) =
                    __floats2half2_rn(acc[mi][ni][0], acc[mi][ni][1]);
            }
            if (gm + 8 < NNODES) {
                *(__half2*)(g_AB + (size_t)(gm + 8) * NOUT + gn) =
                    __floats2half2_rn(acc[mi][ni][2], acc[mi][ni][3]);
            }
        }
    }
}

// ---------------------------------------------------------------------------
// Kernel 2: per-edge MLP tail, packed half2 math.
// 4 edges per warp; folded butterfly reduce (9 shfl for 8 sums) and
// parallel per-lane epilogue (lanes 0/4/8/12 each own one edge).
// ---------------------------------------------------------------------------
__global__ __launch_bounds__(256) void edge_kernel(const float* __restrict__ b1,
                                                   const float* __restrict__ W2,
                                                   const float* __restrict__ b2,
                                                   const float* __restrict__ cw,
                                                   const int* __restrict__ esrc,
                                                   const int* __restrict__ edst,
                                                   const int* __restrict__ labels,
                                                   float* __restrict__ out)
{
    __shared__ __half2 s_b1h[D1DIM / 2];
    __shared__ __half2 s_w0h[D1DIM / 2];
    __shared__ __half2 s_w1h[D1DIM / 2];
    __shared__ float s_wn[EDGE_WARPS];
    __shared__ float s_w[EDGE_WARPS];

    const int tid  = threadIdx.x;
    const int lane = tid & 31;
    const int warp = tid >> 5;

    if (tid < D1DIM / 2) {
        s_b1h[tid] = __floats2half2_rn(b1[2 * tid], b1[2 * tid + 1]);
        s_w0h[tid] = __floats2half2_rn(W2[2 * tid], W2[2 * tid + 1]);
        s_w1h[tid] = __floats2half2_rn(W2[D1DIM + 2 * tid], W2[D1DIM + 2 * tid + 1]);
    }
    __syncthreads();

    const int eb = blockIdx.x * EDGES_PER_BLOCK + warp * EDGES_PER_WARP;
    const int j0 = lane * 8;          // 8 halves = 4 half2 per lane
    const int h0 = lane * 4;          // half2 base index

    // issue all 8 gathers before compute
    uint4 va[EDGES_PER_WARP], vb[EDGES_PER_WARP];
    #pragma unroll
    for (int q = 0; q < EDGES_PER_WARP; q++) {
        const int s = esrc[eb + q];
        const int d = edst[eb + q];
        va[q] = *(const uint4*)(g_AB + (size_t)s * NOUT + j0);
        vb[q] = *(const uint4*)(g_AB + (size_t)d * NOUT + D1DIM + j0);
    }

    const __half2 C0  = __float2half2_rn(0.7978845608f);
    const __half2 C1  = __float2half2_rn(0.0356774081f);
    const __half2 H05 = __float2half2_rn(0.5f);

    __half2 ac0[EDGES_PER_WARP], ac1[EDGES_PER_WARP];
    #pragma unroll
    for (int q = 0; q < EDGES_PER_WARP; q++) {
        ac0[q] = __float2half2_rn(0.f);
        ac1[q] = __float2half2_rn(0.f);
    }

    #pragma unroll
    for (int t = 0; t < 4; t++) {
        const __half2 bh = s_b1h[h0 + t];
        const __half2 w0 = s_w0h[h0 + t];
        const __half2 w1 = s_w1h[h0 + t];
        #pragma unroll
        for (int q = 0; q < EDGES_PER_WARP; q++) {
            const __half2 a2 = ((const __half2*)&va[q])[t];
            const __half2 b2h = ((const __half2*)&vb[q])[t];
            const __half2 v  = __hadd2(__hadd2(a2, b2h), bh);
            const __half2 w  = __hmul2(v, v);
            const __half2 u  = __hmul2(v, __hfma2(C1, w, C0));
            const __half2 th = tanh_h2(u);
            const __half2 hv = __hmul2(H05, v);
            const __half2 h  = __hfma2(hv, th, hv);
            ac0[q] = __hfma2(h, w0, ac0[q]);
            ac1[q] = __hfma2(h, w1, ac1[q]);
        }
    }

    // widen per-lane half2 accumulators (only 4 fp16 fma terms each) to fp32
    // r[i] = f0 of edge i (i<4), r[i+4] = f1 of edge i
    float r[8];
    #pragma unroll
    for (int q = 0; q < EDGES_PER_WARP; q++) {
        const float2 x0 = __half22float2(ac0[q]);
        const float2 x1 = __half22float2(ac1[q]);
        r[q]     = x0.x + x0.y;
        r[q + 4] = x1.x + x1.y;
    }

    // ---- folded butterfly reduce: 8 values over 32 lanes in 9 shfl ----
    // after fold, lane identity idx = (bit4?4:0)|(bit3?2:0)|(bit2?1:0):
    //   lanes 4q  (q=0..3) hold f0[q]; lanes 16+4q hold f1[q]
    #pragma unroll
    for (int i = 0; i < 4; i++) {                       // xor 16: 8 -> 4
        const float keep = (lane & 16) ? r[i + 4] : r[i];
        const float send = (lane & 16) ? r[i] : r[i + 4];
        r[i] = keep + __shfl_xor_sync(0xFFFFFFFFu, send, 16);
    }
    #pragma unroll
    for (int i = 0; i < 2; i++) {                       // xor 8: 4 -> 2
        const float keep = (lane & 8) ? r[i + 2] : r[i];
        const float send = (lane & 8) ? r[i] : r[i + 2];
        r[i] = keep + __shfl_xor_sync(0xFFFFFFFFu, send, 8);
    }
    {                                                   // xor 4: 2 -> 1
        const float keep = (lane & 4) ? r[1] : r[0];
        const float send = (lane & 4) ? r[0] : r[1];
        r[0] = keep + __shfl_xor_sync(0xFFFFFFFFu, send, 4);
    }
    r[0] += __shfl_xor_sync(0xFFFFFFFFu, r[0], 2);
    r[0] += __shfl_xor_sync(0xFFFFFFFFu, r[0], 1);

    // pair the two logits: lane 4q gets f1[q] from lane 16+4q
    const float fother = __shfl_xor_sync(0xFFFFFFFFu, r[0], 16);

    // ---- parallel epilogue on lanes 0,4,8,12 ----
    float wn = 0.f, wsum = 0.f;
    if ((lane & 19) == 0) {                 // bits 0,1,4 clear: lanes 0,4,8,12
        const int q = lane >> 2;
        const int e = eb + q;
        const float l0 = r[0]   + __ldg(&b2[0]);
        const float l1 = fother + __ldg(&b2[1]);
        const float m  = fmaxf(l0, l1);
        const float x0 = expf(l0 - m), x1 = expf(l1 - m);
        const float ssum = x0 + x1, inv = 1.0f / ssum;
        out[1 + 2 * e]     = x0 * inv;
        out[1 + 2 * e + 1] = x1 * inv;
        const int lb = labels[e];
        const float logp = ((lb ? l1 : l0) - m) - logf(ssum);
        const float w = __ldg(&cw[lb]);
        wn   = -w * logp;
        wsum = w;
    }
    // sum wn/wsum over lanes {0,4,8,12} (others contribute 0)
    wn   += __shfl_xor_sync(0xFFFFFFFFu, wn, 4);
    wsum += __shfl_xor_sync(0xFFFFFFFFu, wsum, 4);
    wn   += __shfl_xor_sync(0xFFFFFFFFu, wn, 8);
    wsum += __shfl_xor_sync(0xFFFFFFFFu, wsum, 8);

    if (lane == 0) { s_wn[warp] = wn; s_w[warp] = wsum; }
    __syncthreads();
    if (tid == 0) {
        float a = 0.f, b = 0.f;
        #pragma unroll
        for (int i = 0; i < EDGE_WARPS; i++) { a += s_wn[i]; b += s_w[i]; }
        g_partials[blockIdx.x]               = a;
        g_partials[EDGE_BLOCKS + blockIdx.x] = b;
    }
}

// ---------------------------------------------------------------------------
// Kernel 3: deterministic final reduction -> loss at out[0]
// ---------------------------------------------------------------------------
__global__ __launch_bounds__(256) void finalize_kernel(float* __restrict__ out)
{
    __shared__ float sa[256];
    __shared__ float sb[256];
    const int tid = threadIdx.x;
    float a = 0.f, b = 0.f;
    for (int i = tid; i < EDGE_BLOCKS; i += 256) {
        a += g_partials[i];
        b += g_partials[EDGE_BLOCKS + i];
    }
    sa[tid] = a; sb[tid] = b;
    __syncthreads();
    for (int o = 128; o > 0; o >>= 1) {
        if (tid < o) { sa[tid] += sa[tid + o]; sb[tid] += sb[tid + o]; }
        __syncthreads();
    }
    if (tid == 0) out[0] = sa[0] / sb[0];
}

// ---------------------------------------------------------------------------
extern "C" void kernel_launch(void* const* d_in, const int* in_sizes, int n_in,
                              void* d_out, int out_size)
{
    const float* x      = (const float*)d_in[0];
    const float* W1     = (const float*)d_in[1];
    const float* b1     = (const float*)d_in[2];
    const float* W2     = (const float*)d_in[3];
    const float* b2     = (const float*)d_in[4];
    const float* cw     = (const float*)d_in[5];
    const int*   esrc   = (const int*)d_in[6];
    const int*   edst   = (const int*)d_in[7];
    const int*   labels = (const int*)d_in[8];
    float* out = (float*)d_out;

    const int GEMM_SMEM = 2 * NSTAGE * STAGE_H * (int)sizeof(__half);  // 61440
    cudaFuncSetAttribute(gemm_kernel,
                         cudaFuncAttributeMaxDynamicSharedMemorySize, GEMM_SMEM);

    const int nx4 = (int)(((size_t)NNODES * HDIM / 4 + 255) / 256);   // 37500
    conv_x_kernel<<<nx4, 256>>>(x);
    conv_w_kernel<<<(NOUT * HDIM / 4 + 255) / 256, 256>>>(W1);

    dim3 ggrid((NNODES + BM - 1) / BM, NOUT / BN);   // 391 x 4
    gemm_kernel<<<ggrid, 256, GEMM_SMEM>>>();
    edge_kernel<<<EDGE_BLOCKS, 256>>>(b1, W2, b2, cw, esrc, edst, labels, out);
    finalize_kernel<<<1, 256>>>(out);
}

// round 13
// speedup vs baseline: 1.2546x; 1.0078x over previous
#include <cuda_runtime.h>
#include <cuda_fp16.h>
#include <math.h>
#include <stdint.h>

// Problem constants (fixed by the dataset)
#define NNODES 50000
#define HDIM   768
#define D1DIM  256
#define NOUT   512        // 2*D1: [A | B] per node
#define NEDGES 200000

// GEMM tiling: 128x128 block, BK=32, fp16 mma.sync m16n8k16, 3-stage cp.async
#define BM 128
#define BN 128
#define BK 32
#define LDH 40            // smem row stride in halves (80B); conflict-free ldmatrix
#define NSTAGE 3
#define STAGE_H (BM * LDH)            // halves per tile stage (5120)

#define EDGE_WARPS 8
#define EDGES_PER_WARP 4
#define EDGES_PER_BLOCK (EDGE_WARPS * EDGES_PER_WARP)     // 32
#define EDGE_BLOCKS (NEDGES / EDGES_PER_BLOCK)            // 6250

// Scratch (static device globals; no runtime allocation)
__device__ __half g_xh[(size_t)NNODES * HDIM];       // x in fp16 (~77 MB)
__device__ __half g_Wh[(size_t)NOUT * HDIM];         // Wcat rows in fp16 (768 KB)
__device__ __half g_AB[(size_t)NNODES * NOUT];       // ~51 MB -> L2-resident
__device__ float  g_partials[2 * EDGE_BLOCKS];

// ---------------------------------------------------------------------------
// helpers
// ---------------------------------------------------------------------------
__device__ __forceinline__ void cp_async16(void* smem, const void* gmem) {
    unsigned s = (unsigned)__cvta_generic_to_shared(smem);
    asm volatile("cp.async.cg.shared.global [%0], [%1], 16;" :: "r"(s), "l"(gmem));
}
#define CP_COMMIT  asm volatile("cp.async.commit_group;")
#define CP_WAIT1   asm volatile("cp.async.wait_group 1;")
#define CP_WAIT0   asm volatile("cp.async.wait_group 0;")

__device__ __forceinline__ void ldsm_x4(unsigned& r0, unsigned& r1,
                                        unsigned& r2, unsigned& r3, unsigned addr) {
    asm volatile("ldmatrix.sync.aligned.m8n8.x4.shared.b16 {%0,%1,%2,%3}, [%4];"
                 : "=r"(r0), "=r"(r1), "=r"(r2), "=r"(r3) : "r"(addr));
}

#define MMA_F16(c, a, b)                                                      \
    asm volatile(                                                             \
        "mma.sync.aligned.m16n8k16.row.col.f32.f16.f16.f32 "                  \
        "{%0,%1,%2,%3},{%4,%5,%6,%7},{%8,%9},{%0,%1,%2,%3};"                  \
        : "+f"((c)[0]), "+f"((c)[1]), "+f"((c)[2]), "+f"((c)[3])              \
        : "r"((a)[0]), "r"((a)[1]), "r"((a)[2]), "r"((a)[3]),                 \
          "r"((b)[0]), "r"((b)[1]))

// packed half2 tanh on the MUFU pipe
__device__ __forceinline__ __half2 tanh_h2(__half2 x) {
    __half2 y;
    asm("tanh.approx.f16x2 %0, %1;"
        : "=r"(reinterpret_cast<unsigned&>(y))
        : "r"(reinterpret_cast<unsigned&>(x)));
    return y;
}

// ---------------------------------------------------------------------------
// Conversion pre-passes: fp32 -> fp16 globals
// ---------------------------------------------------------------------------
__global__ __launch_bounds__(256) void conv_x_kernel(const float* __restrict__ x)
{
    const size_t i = (size_t)blockIdx.x * 256 + threadIdx.x;   // float4 index
    const size_t n4 = (size_t)NNODES * HDIM / 4;
    if (i < n4) {
        float4 v = *(const float4*)(x + i * 4);
        __half2 h0 = __floats2half2_rn(v.x, v.y);
        __half2 h1 = __floats2half2_rn(v.z, v.w);
        uint2 o; o.x = *(uint32_t*)&h0; o.y = *(uint32_t*)&h1;
        *(uint2*)(g_xh + i * 4) = o;
    }
}

__global__ __launch_bounds__(256) void conv_w_kernel(const float* __restrict__ W1)
{
    const int i = blockIdx.x * 256 + threadIdx.x;   // float4 index
    const int n4 = NOUT * HDIM / 4;
    if (i < n4) {
        const int e = i * 4;
        const int n = e / HDIM;
        const int k = e % HDIM;
        const float* src = (n < D1DIM)
            ? (W1 + (size_t)n * (2 * HDIM) + k)
            : (W1 + (size_t)(n - D1DIM) * (2 * HDIM) + HDIM + k);
        float4 v = *(const float4*)src;
        __half2 h0 = __floats2half2_rn(v.x, v.y);
        __half2 h1 = __floats2half2_rn(v.z, v.w);
        uint2 o; o.x = *(uint32_t*)&h0; o.y = *(uint32_t*)&h1;
        *(uint2*)(g_Wh + e) = o;
    }
}

// ---------------------------------------------------------------------------
// Kernel 1: AB = x_h @ W_h^T via fp16 mma.sync m16n8k16 (fp32 accumulate).
// 3-stage cp.async pipeline, ldmatrix.x4 b16 fragment loads (benched fastest;
// GEMM runs at ~93% of the fp16 HMMA pipe ceiling).
// ---------------------------------------------------------------------------
__global__ __launch_bounds__(256) void gemm_kernel()
{
    extern __shared__ __align__(16) __half smem[];
    __half* sA = smem;
    __half* sB = smem + NSTAGE * STAGE_H;

    const int tid  = threadIdx.x;
    const int lane = tid & 31;
    const int warp = tid >> 5;
    const int wm   = (warp >> 2) * 64;
    const int wn   = (warp & 3) * 32;

    const int m0 = blockIdx.x * BM;
    const int n0 = blockIdx.y * BN;

    const int row0 = tid >> 2;             // 0..63
    const int c4   = tid & 3;
    const int row1 = row0 + 64;
    int gm0 = m0 + row0; if (gm0 > NNODES - 1) gm0 = NNODES - 1;
    int gm1 = m0 + row1; if (gm1 > NNODES - 1) gm1 = NNODES - 1;
    const __half* pA0 = g_xh + (size_t)gm0 * HDIM + c4 * 8;
    const __half* pA1 = g_xh + (size_t)gm1 * HDIM + c4 * 8;
    const __half* pB0 = g_Wh + (size_t)(n0 + row0) * HDIM + c4 * 8;
    const __half* pB1 = g_Wh + (size_t)(n0 + row1) * HDIM + c4 * 8;

    unsigned smA[NSTAGE], smB[NSTAGE];
    #pragma unroll
    for (int st = 0; st < NSTAGE; st++) {
        smA[st] = (unsigned)__cvta_generic_to_shared(sA + st * STAGE_H);
        smB[st] = (unsigned)__cvta_generic_to_shared(sB + st * STAGE_H);
    }

    const int aRow = wm + (lane & 15);
    const unsigned aKB = (unsigned)(lane >> 4) * 16u;
    const int bRow = wn + ((lane >> 4) & 1) * 8 + (lane & 7);
    const unsigned bKB = (unsigned)((lane >> 3) & 1) * 16u;

    float acc[4][4][4];
    #pragma unroll
    for (int i = 0; i < 4; i++)
        #pragma unroll
        for (int j = 0; j < 4; j++)
            #pragma unroll
            for (int v = 0; v < 4; v++) acc[i][j][v] = 0.f;

    #pragma unroll
    for (int st = 0; st < 2; st++) {
        const int kt = st * BK;
        cp_async16(sA + st * STAGE_H + row0 * LDH + c4 * 8, pA0 + kt);
        cp_async16(sA + st * STAGE_H + row1 * LDH + c4 * 8, pA1 + kt);
        cp_async16(sB + st * STAGE_H + row0 * LDH + c4 * 8, pB0 + kt);
        cp_async16(sB + st * STAGE_H + row1 * LDH + c4 * 8, pB1 + kt);
        CP_COMMIT;
    }

    const int NIT = HDIM / BK;  // 24
    int s = 0;
    for (int it = 0; it < NIT; ++it) {
        if (it < NIT - 1) { CP_WAIT1; } else { CP_WAIT0; }
        __syncthreads();

        if (it + 2 < NIT) {
            const int st = (it + 2) % NSTAGE;
            const int kt = (it + 2) * BK;
            cp_async16(sA + st * STAGE_H + row0 * LDH + c4 * 8, pA0 + kt);
            cp_async16(sA + st * STAGE_H + row1 * LDH + c4 * 8, pA1 + kt);
            cp_async16(sB + st * STAGE_H + row0 * LDH + c4 * 8, pB0 + kt);
            cp_async16(sB + st * STAGE_H + row1 * LDH + c4 * 8, pB1 + kt);
            CP_COMMIT;
        }

        const unsigned bA = smA[s];
        const unsigned bB = smB[s];
        #pragma unroll
        for (int kk = 0; kk < 2; kk++) {
            unsigned af[4][4], bf[4][2];
            #pragma unroll
            for (int mi = 0; mi < 4; mi++) {
                unsigned addr = bA + (unsigned)(aRow + mi * 16) * (LDH * 2)
                              + (unsigned)kk * 32u + aKB;
                ldsm_x4(af[mi][0], af[mi][1], af[mi][2], af[mi][3], addr);
            }
            #pragma unroll
            for (int p = 0; p < 2; p++) {
                unsigned addr = bB + (unsigned)(bRow + p * 16) * (LDH * 2)
                              + (unsigned)kk * 32u + bKB;
                ldsm_x4(bf[2 * p][0], bf[2 * p][1], bf[2 * p + 1][0], bf[2 * p + 1][1], addr);
            }
            #pragma unroll
            for (int mi = 0; mi < 4; mi++)
                #pragma unroll
                for (int ni = 0; ni < 4; ni++)
                    MMA_F16(acc[mi][ni], af[mi], bf[ni]);
        }
        s = (s + 1 == NSTAGE) ? 0 : s + 1;
    }

    const int g  = lane >> 2;
    const int tg = lane & 3;
    #pragma unroll
    for (int mi = 0; mi < 4; mi++) {
        #pragma unroll
        for (int ni = 0; ni < 4; ni++) {
            const int gm = m0 + wm + mi * 16 + g;
            const int gn = n0 + wn + ni * 8 + 2 * tg;
            if (gm < NNODES) {
                *(__half2*)(g_AB + (size_t)gm * NOUT + gn) =
                    __floats2half2_rn(acc[mi][ni][0], acc[mi][ni][1]);
            }
            if (gm + 8 < NNODES) {
                *(__half2*)(g_AB + (size_t)(gm + 8) * NOUT + gn) =
                    __floats2half2_rn(acc[mi][ni][2], acc[mi][ni][3]);
            }
        }
    }
}

// ---------------------------------------------------------------------------
// Kernel 2: per-edge MLP tail, packed half2 math, LOGIT-DIFFERENCE form.
// For C=2: d = l1-l0 = sum h*(w1-w0) + (b2[1]-b2[0]); p1 = sigmoid(d);
// nll = -log(p_label). One accumulator per edge; 4 edges/warp.
// ---------------------------------------------------------------------------
__global__ __launch_bounds__(256) void edge_kernel(const float* __restrict__ b1,
                                                   const float* __restrict__ W2,
                                                   const float* __restrict__ b2,
                                                   const float* __restrict__ cw,
                                                   const int* __restrict__ esrc,
                                                   const int* __restrict__ edst,
                                                   const int* __restrict__ labels,
                                                   float* __restrict__ out)
{
    __shared__ __half2 s_b1h[D1DIM / 2];
    __shared__ __half2 s_wdh[D1DIM / 2];     // w1 - w0 (fp32 diff -> fp16)
    __shared__ float s_wn[EDGE_WARPS];
    __shared__ float s_w[EDGE_WARPS];

    const int tid  = threadIdx.x;
    const int lane = tid & 31;
    const int warp = tid >> 5;

    if (tid < D1DIM / 2) {
        s_b1h[tid] = __floats2half2_rn(b1[2 * tid], b1[2 * tid + 1]);
        s_wdh[tid] = __floats2half2_rn(W2[D1DIM + 2 * tid] - W2[2 * tid],
                                       W2[D1DIM + 2 * tid + 1] - W2[2 * tid + 1]);
    }
    __syncthreads();

    const int eb = blockIdx.x * EDGES_PER_BLOCK + warp * EDGES_PER_WARP;
    const int j0 = lane * 8;          // 8 halves = 4 half2 per lane
    const int h0 = lane * 4;          // half2 base index

    // issue all 8 gathers before compute
    uint4 va[EDGES_PER_WARP], vb[EDGES_PER_WARP];
    #pragma unroll
    for (int q = 0; q < EDGES_PER_WARP; q++) {
        const int s = esrc[eb + q];
        const int d = edst[eb + q];
        va[q] = *(const uint4*)(g_AB + (size_t)s * NOUT + j0);
        vb[q] = *(const uint4*)(g_AB + (size_t)d * NOUT + D1DIM + j0);
    }

    const __half2 C0  = __float2half2_rn(0.7978845608f);
    const __half2 C1  = __float2half2_rn(0.0356774081f);
    const __half2 H05 = __float2half2_rn(0.5f);

    __half2 acd[EDGES_PER_WARP];
    #pragma unroll
    for (int q = 0; q < EDGES_PER_WARP; q++) acd[q] = __float2half2_rn(0.f);

    #pragma unroll
    for (int t = 0; t < 4; t++) {
        const __half2 bh = s_b1h[h0 + t];
        const __half2 wd = s_wdh[h0 + t];
        #pragma unroll
        for (int q = 0; q < EDGES_PER_WARP; q++) {
            const __half2 a2 = ((const __half2*)&va[q])[t];
            const __half2 b2h = ((const __half2*)&vb[q])[t];
            const __half2 v  = __hadd2(__hadd2(a2, b2h), bh);
            const __half2 w  = __hmul2(v, v);
            const __half2 u  = __hmul2(v, __hfma2(C1, w, C0));
            const __half2 th = tanh_h2(u);
            const __half2 hv = __hmul2(H05, v);
            const __half2 h  = __hfma2(hv, th, hv);
            acd[q] = __hfma2(h, wd, acd[q]);
        }
    }

    // widen per-lane half2 accumulators to fp32: r[q] = d-partial of edge q
    float r[EDGES_PER_WARP];
    #pragma unroll
    for (int q = 0; q < EDGES_PER_WARP; q++) {
        const float2 x = __half22float2(acd[q]);
        r[q] = x.x + x.y;
    }

    // ---- folded butterfly reduce: 4 values over 32 lanes ----
    // after folds, lane l holds edge ((l>>4)&1)*2 + ((l>>3)&1)
    #pragma unroll
    for (int i = 0; i < 2; i++) {                       // xor 16: 4 -> 2
        const float keep = (lane & 16) ? r[i + 2] : r[i];
        const float send = (lane & 16) ? r[i] : r[i + 2];
        r[i] = keep + __shfl_xor_sync(0xFFFFFFFFu, send, 16);
    }
    {                                                   // xor 8: 2 -> 1
        const float keep = (lane & 8) ? r[1] : r[0];
        const float send = (lane & 8) ? r[0] : r[1];
        r[0] = keep + __shfl_xor_sync(0xFFFFFFFFu, send, 8);
    }
    r[0] += __shfl_xor_sync(0xFFFFFFFFu, r[0], 4);
    r[0] += __shfl_xor_sync(0xFFFFFFFFu, r[0], 2);
    r[0] += __shfl_xor_sync(0xFFFFFFFFu, r[0], 1);

    // ---- parallel epilogue: lanes 0,8,16,24 each own one edge ----
    float wn = 0.f, wsum = 0.f;
    if ((lane & 7) == 0) {
        const int q = ((lane >> 4) & 1) * 2 + ((lane >> 3) & 1);
        const int e = eb + q;
        const float d = r[0] + (__ldg(&b2[1]) - __ldg(&b2[0]));
        // stable sigmoid pair
        const float ed  = __expf(-fabsf(d));
        const float inv = 1.0f / (1.0f + ed);
        const float pmx = inv;            // prob of larger logit
        const float pmn = ed * inv;       // prob of smaller logit
        const float p1 = (d >= 0.f) ? pmx : pmn;
        const float p0 = (d >= 0.f) ? pmn : pmx;
        out[1 + 2 * e]     = p0;
        out[1 + 2 * e + 1] = p1;
        const int lb = labels[e];
        const float py = lb ? p1 : p0;
        const float w  = __ldg(&cw[lb]);
        wn   = -w * logf(py);
        wsum = w;
    }
    // sum over lanes {0,8,16,24} (others are 0)
    wn   += __shfl_xor_sync(0xFFFFFFFFu, wn, 8);
    wsum += __shfl_xor_sync(0xFFFFFFFFu, wsum, 8);
    wn   += __shfl_xor_sync(0xFFFFFFFFu, wn, 16);
    wsum += __shfl_xor_sync(0xFFFFFFFFu, wsum, 16);

    if (lane == 0) { s_wn[warp] = wn; s_w[warp] = wsum; }
    __syncthreads();
    if (tid == 0) {
        float a = 0.f, b = 0.f;
        #pragma unroll
        for (int i = 0; i < EDGE_WARPS; i++) { a += s_wn[i]; b += s_w[i]; }
        g_partials[blockIdx.x]               = a;
        g_partials[EDGE_BLOCKS + blockIdx.x] = b;
    }
}

// ---------------------------------------------------------------------------
// Kernel 3: deterministic final reduction -> loss at out[0]
// ---------------------------------------------------------------------------
__global__ __launch_bounds__(256) void finalize_kernel(float* __restrict__ out)
{
    __shared__ float sa[256];
    __shared__ float sb[256];
    const int tid = threadIdx.x;
    float a = 0.f, b = 0.f;
    for (int i = tid; i < EDGE_BLOCKS; i += 256) {
        a += g_partials[i];
        b += g_partials[EDGE_BLOCKS + i];
    }
    sa[tid] = a; sb[tid] = b;
    __syncthreads();
    for (int o = 128; o > 0; o >>= 1) {
        if (tid < o) { sa[tid] += sa[tid + o]; sb[tid] += sb[tid + o]; }
        __syncthreads();
    }
    if (tid == 0) out[0] = sa[0] / sb[0];
}

// ---------------------------------------------------------------------------
extern "C" void kernel_launch(void* const* d_in, const int* in_sizes, int n_in,
                              void* d_out, int out_size)
{
    const float* x      = (const float*)d_in[0];
    const float* W1     = (const float*)d_in[1];
    const float* b1     = (const float*)d_in[2];
    const float* W2     = (const float*)d_in[3];
    const float* b2     = (const float*)d_in[4];
    const float* cw     = (const float*)d_in[5];
    const int*   esrc   = (const int*)d_in[6];
    const int*   edst   = (const int*)d_in[7];
    const int*   labels = (const int*)d_in[8];
    float* out = (float*)d_out;

    const int GEMM_SMEM = 2 * NSTAGE * STAGE_H * (int)sizeof(__half);  // 61440
    cudaFuncSetAttribute(gemm_kernel,
                         cudaFuncAttributeMaxDynamicSharedMemorySize, GEMM_SMEM);

    const int nx4 = (int)(((size_t)NNODES * HDIM / 4 + 255) / 256);   // 37500
    conv_x_kernel<<<nx4, 256>>>(x);
    conv_w_kernel<<<(NOUT * HDIM / 4 + 255) / 256, 256>>>(W1);

    dim3 ggrid((NNODES + BM - 1) / BM, NOUT / BN);   // 391 x 4
    gemm_kernel<<<ggrid, 256, GEMM_SMEM>>>();
    edge_kernel<<<EDGE_BLOCKS, 256>>>(b1, W2, b2, cw, esrc, edst, labels, out);
    finalize_kernel<<<1, 256>>>(out);
}

// round 14
// speedup vs baseline: 1.2666x; 1.0095x over previous
#include <cuda_runtime.h>
#include <cuda_fp16.h>
#include <math.h>
#include <stdint.h>

// Problem constants (fixed by the dataset)
#define NNODES 50000
#define HDIM   768
#define D1DIM  256
#define NOUT   512        // 2*D1: [A | B] per node
#define NEDGES 200000

// GEMM tiling: 128x128 block, BK=32, fp16 mma.sync m16n8k16, 3-stage cp.async
#define BM 128
#define BN 128
#define BK 32
#define LDH 40            // smem row stride in halves (80B); conflict-free ldmatrix
#define NSTAGE 3
#define STAGE_H (BM * LDH)            // halves per tile stage (5120)

#define EDGE_WARPS 8
#define EDGES_PER_WARP 4
#define EDGES_PER_BLOCK (EDGE_WARPS * EDGES_PER_WARP)     // 32
#define EDGE_BLOCKS (NEDGES / EDGES_PER_BLOCK)            // 6250

// conv_x: 4 strided float4 per thread for MLP
#define CVX_UNROLL 4
#define CVX_N4 ((size_t)NNODES * HDIM / 4)                // 9,600,000 float4
#define CVX_BLOCKS ((int)((CVX_N4 + 256 * CVX_UNROLL - 1) / (256 * CVX_UNROLL)))

// Scratch (static device globals; no runtime allocation)
__device__ __half g_xh[(size_t)NNODES * HDIM];       // x in fp16 (~77 MB)
__device__ __half g_Wh[(size_t)NOUT * HDIM];         // Wcat rows in fp16 (768 KB)
__device__ __half g_AB[(size_t)NNODES * NOUT];       // ~51 MB -> L2-resident
__device__ float  g_partials[2 * EDGE_BLOCKS];

// ---------------------------------------------------------------------------
// helpers
// ---------------------------------------------------------------------------
__device__ __forceinline__ void cp_async16(void* smem, const void* gmem) {
    unsigned s = (unsigned)__cvta_generic_to_shared(smem);
    asm volatile("cp.async.cg.shared.global [%0], [%1], 16;" :: "r"(s), "l"(gmem));
}
#define CP_COMMIT  asm volatile("cp.async.commit_group;")
#define CP_WAIT1   asm volatile("cp.async.wait_group 1;")
#define CP_WAIT0   asm volatile("cp.async.wait_group 0;")

__device__ __forceinline__ void ldsm_x4(unsigned& r0, unsigned& r1,
                                        unsigned& r2, unsigned& r3, unsigned addr) {
    asm volatile("ldmatrix.sync.aligned.m8n8.x4.shared.b16 {%0,%1,%2,%3}, [%4];"
                 : "=r"(r0), "=r"(r1), "=r"(r2), "=r"(r3) : "r"(addr));
}

#define MMA_F16(c, a, b)                                                      \
    asm volatile(                                                             \
        "mma.sync.aligned.m16n8k16.row.col.f32.f16.f16.f32 "                  \
        "{%0,%1,%2,%3},{%4,%5,%6,%7},{%8,%9},{%0,%1,%2,%3};"                  \
        : "+f"((c)[0]), "+f"((c)[1]), "+f"((c)[2]), "+f"((c)[3])              \
        : "r"((a)[0]), "r"((a)[1]), "r"((a)[2]), "r"((a)[3]),                 \
          "r"((b)[0]), "r"((b)[1]))

// packed half2 tanh on the MUFU pipe
__device__ __forceinline__ __half2 tanh_h2(__half2 x) {
    __half2 y;
    asm("tanh.approx.f16x2 %0, %1;"
        : "=r"(reinterpret_cast<unsigned&>(y))
        : "r"(reinterpret_cast<unsigned&>(x)));
    return y;
}

// ---------------------------------------------------------------------------
// Conversion pre-passes: fp32 -> fp16 globals
// ---------------------------------------------------------------------------
__global__ __launch_bounds__(256) void conv_x_kernel(const float* __restrict__ x)
{
    const size_t stride = (size_t)CVX_BLOCKS * 256;
    size_t i = (size_t)blockIdx.x * 256 + threadIdx.x;
    // issue all loads first (MLP=4), then convert+store
    float4 v[CVX_UNROLL];
    bool ok[CVX_UNROLL];
    size_t idx[CVX_UNROLL];
    #pragma unroll
    for (int u = 0; u < CVX_UNROLL; u++) {
        idx[u] = i + (size_t)u * stride;
        ok[u]  = idx[u] < CVX_N4;
        if (ok[u]) v[u] = *(const float4*)(x + idx[u] * 4);
    }
    #pragma unroll
    for (int u = 0; u < CVX_UNROLL; u++) {
        if (ok[u]) {
            __half2 h0 = __floats2half2_rn(v[u].x, v[u].y);
            __half2 h1 = __floats2half2_rn(v[u].z, v[u].w);
            uint2 o; o.x = *(uint32_t*)&h0; o.y = *(uint32_t*)&h1;
            *(uint2*)(g_xh + idx[u] * 4) = o;
        }
    }
}

__global__ __launch_bounds__(256) void conv_w_kernel(const float* __restrict__ W1)
{
    const int i = blockIdx.x * 256 + threadIdx.x;   // float4 index
    const int n4 = NOUT * HDIM / 4;
    if (i < n4) {
        const int e = i * 4;
        const int n = e / HDIM;
        const int k = e % HDIM;
        const float* src = (n < D1DIM)
            ? (W1 + (size_t)n * (2 * HDIM) + k)
            : (W1 + (size_t)(n - D1DIM) * (2 * HDIM) + HDIM + k);
        float4 v = *(const float4*)src;
        __half2 h0 = __floats2half2_rn(v.x, v.y);
        __half2 h1 = __floats2half2_rn(v.z, v.w);
        uint2 o; o.x = *(uint32_t*)&h0; o.y = *(uint32_t*)&h1;
        *(uint2*)(g_Wh + e) = o;
    }
}

// ---------------------------------------------------------------------------
// Kernel 1: AB = x_h @ W_h^T via fp16 mma.sync m16n8k16 (fp32 accumulate).
// 3-stage cp.async pipeline, ldmatrix.x4 b16 fragment loads.
// Epilogue folds b1 into the A-half (n0 < 256) in fp32 before fp16 rounding.
// ---------------------------------------------------------------------------
__global__ __launch_bounds__(256) void gemm_kernel(const float* __restrict__ b1)
{
    extern __shared__ __align__(16) __half smem[];
    __half* sA = smem;
    __half* sB = smem + NSTAGE * STAGE_H;

    const int tid  = threadIdx.x;
    const int lane = tid & 31;
    const int warp = tid >> 5;
    const int wm   = (warp >> 2) * 64;
    const int wn   = (warp & 3) * 32;

    const int m0 = blockIdx.x * BM;
    const int n0 = blockIdx.y * BN;

    const int row0 = tid >> 2;             // 0..63
    const int c4   = tid & 3;
    const int row1 = row0 + 64;
    int gm0 = m0 + row0; if (gm0 > NNODES - 1) gm0 = NNODES - 1;
    int gm1 = m0 + row1; if (gm1 > NNODES - 1) gm1 = NNODES - 1;
    const __half* pA0 = g_xh + (size_t)gm0 * HDIM + c4 * 8;
    const __half* pA1 = g_xh + (size_t)gm1 * HDIM + c4 * 8;
    const __half* pB0 = g_Wh + (size_t)(n0 + row0) * HDIM + c4 * 8;
    const __half* pB1 = g_Wh + (size_t)(n0 + row1) * HDIM + c4 * 8;

    unsigned smA[NSTAGE], smB[NSTAGE];
    #pragma unroll
    for (int st = 0; st < NSTAGE; st++) {
        smA[st] = (unsigned)__cvta_generic_to_shared(sA + st * STAGE_H);
        smB[st] = (unsigned)__cvta_generic_to_shared(sB + st * STAGE_H);
    }

    const int aRow = wm + (lane & 15);
    const unsigned aKB = (unsigned)(lane >> 4) * 16u;
    const int bRow = wn + ((lane >> 4) & 1) * 8 + (lane & 7);
    const unsigned bKB = (unsigned)((lane >> 3) & 1) * 16u;

    float acc[4][4][4];
    #pragma unroll
    for (int i = 0; i < 4; i++)
        #pragma unroll
        for (int j = 0; j < 4; j++)
            #pragma unroll
            for (int v = 0; v < 4; v++) acc[i][j][v] = 0.f;

    #pragma unroll
    for (int st = 0; st < 2; st++) {
        const int kt = st * BK;
        cp_async16(sA + st * STAGE_H + row0 * LDH + c4 * 8, pA0 + kt);
        cp_async16(sA + st * STAGE_H + row1 * LDH + c4 * 8, pA1 + kt);
        cp_async16(sB + st * STAGE_H + row0 * LDH + c4 * 8, pB0 + kt);
        cp_async16(sB + st * STAGE_H + row1 * LDH + c4 * 8, pB1 + kt);
        CP_COMMIT;
    }

    const int NIT = HDIM / BK;  // 24
    int s = 0;
    for (int it = 0; it < NIT; ++it) {
        if (it < NIT - 1) { CP_WAIT1; } else { CP_WAIT0; }
        __syncthreads();

        if (it + 2 < NIT) {
            const int st = (it + 2) % NSTAGE;
            const int kt = (it + 2) * BK;
            cp_async16(sA + st * STAGE_H + row0 * LDH + c4 * 8, pA0 + kt);
            cp_async16(sA + st * STAGE_H + row1 * LDH + c4 * 8, pA1 + kt);
            cp_async16(sB + st * STAGE_H + row0 * LDH + c4 * 8, pB0 + kt);
            cp_async16(sB + st * STAGE_H + row1 * LDH + c4 * 8, pB1 + kt);
            CP_COMMIT;
        }

        const unsigned bA = smA[s];
        const unsigned bB = smB[s];
        #pragma unroll
        for (int kk = 0; kk < 2; kk++) {
            unsigned af[4][4], bf[4][2];
            #pragma unroll
            for (int mi = 0; mi < 4; mi++) {
                unsigned addr = bA + (unsigned)(aRow + mi * 16) * (LDH * 2)
                              + (unsigned)kk * 32u + aKB;
                ldsm_x4(af[mi][0], af[mi][1], af[mi][2], af[mi][3], addr);
            }
            #pragma unroll
            for (int p = 0; p < 2; p++) {
                unsigned addr = bB + (unsigned)(bRow + p * 16) * (LDH * 2)
                              + (unsigned)kk * 32u + bKB;
                ldsm_x4(bf[2 * p][0], bf[2 * p][1], bf[2 * p + 1][0], bf[2 * p + 1][1], addr);
            }
            #pragma unroll
            for (int mi = 0; mi < 4; mi++)
                #pragma unroll
                for (int ni = 0; ni < 4; ni++)
                    MMA_F16(acc[mi][ni], af[mi], bf[ni]);
        }
        s = (s + 1 == NSTAGE) ? 0 : s + 1;
    }

    // ---- epilogue: fold b1 into A-half, store fp16 ----
    const int g  = lane >> 2;
    const int tg = lane & 3;
    const bool isA = (n0 < D1DIM);         // uniform per block (BN=128)
    float2 bv[4];
    #pragma unroll
    for (int ni = 0; ni < 4; ni++) {
        const int gn = n0 + wn + ni * 8 + 2 * tg;
        bv[ni] = isA ? *(const float2*)(b1 + gn) : make_float2(0.f, 0.f);
    }
    #pragma unroll
    for (int mi = 0; mi < 4; mi++) {
        #pragma unroll
        for (int ni = 0; ni < 4; ni++) {
            const int gm = m0 + wm + mi * 16 + g;
            const int gn = n0 + wn + ni * 8 + 2 * tg;
            if (gm < NNODES) {
                *(__half2*)(g_AB + (size_t)gm * NOUT + gn) =
                    __floats2half2_rn(acc[mi][ni][0] + bv[ni].x,
                                      acc[mi][ni][1] + bv[ni].y);
            }
            if (gm + 8 < NNODES) {
                *(__half2*)(g_AB + (size_t)(gm + 8) * NOUT + gn) =
                    __floats2half2_rn(acc[mi][ni][2] + bv[ni].x,
                                      acc[mi][ni][3] + bv[ni].y);
            }
        }
    }
}

// ---------------------------------------------------------------------------
// Kernel 2: per-edge MLP tail, packed half2, logit-difference form.
// b1 pre-folded into AB's A-half; 0.5 of gelu folded into wd.
// 7 instructions per half2 in the inner loop.
// ---------------------------------------------------------------------------
__global__ __launch_bounds__(256) void edge_kernel(const float* __restrict__ W2,
                                                   const float* __restrict__ b2,
                                                   const float* __restrict__ cw,
                                                   const int* __restrict__ esrc,
                                                   const int* __restrict__ edst,
                                                   const int* __restrict__ labels,
                                                   float* __restrict__ out)
{
    __shared__ __half2 s_wdh[D1DIM / 2];     // 0.5*(w1 - w0) in fp16
    __shared__ float s_wn[EDGE_WARPS];
    __shared__ float s_w[EDGE_WARPS];

    const int tid  = threadIdx.x;
    const int lane = tid & 31;
    const int warp = tid >> 5;

    if (tid < D1DIM / 2) {
        s_wdh[tid] = __floats2half2_rn(
            0.5f * (W2[D1DIM + 2 * tid]     - W2[2 * tid]),
            0.5f * (W2[D1DIM + 2 * tid + 1] - W2[2 * tid + 1]));
    }
    __syncthreads();

    const int eb = blockIdx.x * EDGES_PER_BLOCK + warp * EDGES_PER_WARP;
    const int j0 = lane * 8;          // 8 halves = 4 half2 per lane
    const int h0 = lane * 4;          // half2 base index

    // issue all 8 gathers before compute
    uint4 va[EDGES_PER_WARP], vb[EDGES_PER_WARP];
    #pragma unroll
    for (int q = 0; q < EDGES_PER_WARP; q++) {
        const int s = esrc[eb + q];
        const int d = edst[eb + q];
        va[q] = *(const uint4*)(g_AB + (size_t)s * NOUT + j0);
        vb[q] = *(const uint4*)(g_AB + (size_t)d * NOUT + D1DIM + j0);
    }

    const __half2 C0 = __float2half2_rn(0.7978845608f);
    const __half2 C1 = __float2half2_rn(0.0356774081f);

    __half2 acd[EDGES_PER_WARP];
    #pragma unroll
    for (int q = 0; q < EDGES_PER_WARP; q++) acd[q] = __float2half2_rn(0.f);

    #pragma unroll
    for (int t = 0; t < 4; t++) {
        const __half2 wd = s_wdh[h0 + t];
        #pragma unroll
        for (int q = 0; q < EDGES_PER_WARP; q++) {
            const __half2 a2  = ((const __half2*)&va[q])[t];   // has b1 folded
            const __half2 b2h = ((const __half2*)&vb[q])[t];
            const __half2 v  = __hadd2(a2, b2h);               // 1
            const __half2 w  = __hmul2(v, v);                  // 2
            const __half2 u  = __hmul2(v, __hfma2(C1, w, C0)); // 3,4
            const __half2 th = tanh_h2(u);                     // 5
            const __half2 h2 = __hfma2(v, th, v);              // 6  (= 2*gelu)
            acd[q] = __hfma2(h2, wd, acd[q]);                  // 7
        }
    }

    // widen per-lane half2 accumulators to fp32: r[q] = d-partial of edge q
    float r[EDGES_PER_WARP];
    #pragma unroll
    for (int q = 0; q < EDGES_PER_WARP; q++) {
        const float2 x = __half22float2(acd[q]);
        r[q] = x.x + x.y;
    }

    // ---- folded butterfly reduce: 4 values over 32 lanes ----
    // after folds, lane l holds edge ((l>>4)&1)*2 + ((l>>3)&1)
    #pragma unroll
    for (int i = 0; i < 2; i++) {                       // xor 16: 4 -> 2
        const float keep = (lane & 16) ? r[i + 2] : r[i];
        const float send = (lane & 16) ? r[i] : r[i + 2];
        r[i] = keep + __shfl_xor_sync(0xFFFFFFFFu, send, 16);
    }
    {                                                   // xor 8: 2 -> 1
        const float keep = (lane & 8) ? r[1] : r[0];
        const float send = (lane & 8) ? r[0] : r[1];
        r[0] = keep + __shfl_xor_sync(0xFFFFFFFFu, send, 8);
    }
    r[0] += __shfl_xor_sync(0xFFFFFFFFu, r[0], 4);
    r[0] += __shfl_xor_sync(0xFFFFFFFFu, r[0], 2);
    r[0] += __shfl_xor_sync(0xFFFFFFFFu, r[0], 1);

    // ---- parallel epilogue: lanes 0,8,16,24 each own one edge ----
    float wn = 0.f, wsum = 0.f;
    if ((lane & 7) == 0) {
        const int q = ((lane >> 4) & 1) * 2 + ((lane >> 3) & 1);
        const int e = eb + q;
        const float d = r[0] + (__ldg(&b2[1]) - __ldg(&b2[0]));
        // stable sigmoid pair
        const float ed  = __expf(-fabsf(d));
        const float inv = 1.0f / (1.0f + ed);
        const float pmx = inv;            // prob of larger logit
        const float pmn = ed * inv;       // prob of smaller logit
        const float p1 = (d >= 0.f) ? pmx : pmn;
        const float p0 = (d >= 0.f) ? pmn : pmx;
        out[1 + 2 * e]     = p0;
        out[1 + 2 * e + 1] = p1;
        const int lb = labels[e];
        const float py = lb ? p1 : p0;
        const float w  = __ldg(&cw[lb]);
        wn   = -w * logf(py);
        wsum = w;
    }
    // sum over lanes {0,8,16,24} (others are 0)
    wn   += __shfl_xor_sync(0xFFFFFFFFu, wn, 8);
    wsum += __shfl_xor_sync(0xFFFFFFFFu, wsum, 8);
    wn   += __shfl_xor_sync(0xFFFFFFFFu, wn, 16);
    wsum += __shfl_xor_sync(0xFFFFFFFFu, wsum, 16);

    if (lane == 0) { s_wn[warp] = wn; s_w[warp] = wsum; }
    __syncthreads();
    if (tid == 0) {
        float a = 0.f, b = 0.f;
        #pragma unroll
        for (int i = 0; i < EDGE_WARPS; i++) { a += s_wn[i]; b += s_w[i]; }
        g_partials[blockIdx.x]               = a;
        g_partials[EDGE_BLOCKS + blockIdx.x] = b;
    }
}

// ---------------------------------------------------------------------------
// Kernel 3: deterministic final reduction -> loss at out[0]
// ---------------------------------------------------------------------------
__global__ __launch_bounds__(256) void finalize_kernel(float* __restrict__ out)
{
    __shared__ float sa[256];
    __shared__ float sb[256];
    const int tid = threadIdx.x;
    float a = 0.f, b = 0.f;
    for (int i = tid; i < EDGE_BLOCKS; i += 256) {
        a += g_partials[i];
        b += g_partials[EDGE_BLOCKS + i];
    }
    sa[tid] = a; sb[tid] = b;
    __syncthreads();
    for (int o = 128; o > 0; o >>= 1) {
        if (tid < o) { sa[tid] += sa[tid + o]; sb[tid] += sb[tid + o]; }
        __syncthreads();
    }
    if (tid == 0) out[0] = sa[0] / sb[0];
}

// ---------------------------------------------------------------------------
extern "C" void kernel_launch(void* const* d_in, const int* in_sizes, int n_in,
                              void* d_out, int out_size)
{
    const float* x      = (const float*)d_in[0];
    const float* W1     = (const float*)d_in[1];
    const float* b1     = (const float*)d_in[2];
    const float* W2     = (const float*)d_in[3];
    const float* b2     = (const float*)d_in[4];
    const float* cw     = (const float*)d_in[5];
    const int*   esrc   = (const int*)d_in[6];
    const int*   edst   = (const int*)d_in[7];
    const int*   labels = (const int*)d_in[8];
    float* out = (float*)d_out;

    const int GEMM_SMEM = 2 * NSTAGE * STAGE_H * (int)sizeof(__half);  // 61440
    cudaFuncSetAttribute(gemm_kernel,
                         cudaFuncAttributeMaxDynamicSharedMemorySize, GEMM_SMEM);

    conv_x_kernel<<<CVX_BLOCKS, 256>>>(x);
    conv_w_kernel<<<(NOUT * HDIM / 4 + 255) / 256, 256>>>(W1);

    dim3 ggrid((NNODES + BM - 1) / BM, NOUT / BN);   // 391 x 4
    gemm_kernel<<<ggrid, 256, GEMM_SMEM>>>(b1);
    edge_kernel<<<EDGE_BLOCKS, 256>>>(W2, b2, cw, esrc, edst, labels, out);
    finalize_kernel<<<1, 256>>>(out);
}